// round 1
// baseline (speedup 1.0000x reference)
#include <cuda_runtime.h>
#include <cuda_bf16.h>
#include <cstdint>

// Problem constants (fixed by the dataset)
#define NN 100000      // nodes
#define EE 3200000     // edges
#define K1 512         // X feature dim
#define HD 256         // hidden dim (W0 cols)
#define FD 64          // classes (W1 cols)

// ---------------- scratch (__device__ globals — no runtime allocs) ----------
__device__ float g_XW0[NN * HD];        // X @ W0            (~102 MB)
__device__ float g_H1[NN * HD];         // relu(A @ XW0)     (~102 MB)
__device__ float g_H1W1[NN * FD];       // H1 @ W1           (~25.6 MB)
__device__ int   g_rowptr[NN + 1];
__device__ int   g_cursor[NN];
__device__ int   g_cnt[NN];
__device__ int   g_ccol[EE];
__device__ float g_cval[EE];

// ---------------- CSR build ------------------------------------------------
__global__ void zero_cnt_kernel() {
    int i = blockIdx.x * blockDim.x + threadIdx.x;
    if (i < NN) g_cnt[i] = 0;
}

__global__ void hist_kernel(const int* __restrict__ rows) {
    int i = blockIdx.x * blockDim.x + threadIdx.x;
    if (i < EE) atomicAdd(&g_cnt[rows[i]], 1);
}

// single-block exclusive scan over NN counts -> rowptr & cursor
__global__ void scan_kernel() {
    __shared__ int sh[1024];
    __shared__ int carry;
    int tid = threadIdx.x;
    if (tid == 0) carry = 0;
    __syncthreads();
    for (int base = 0; base < NN; base += 1024) {
        int i = base + tid;
        int x = (i < NN) ? g_cnt[i] : 0;
        sh[tid] = x;
        __syncthreads();
        #pragma unroll
        for (int off = 1; off < 1024; off <<= 1) {
            int t = (tid >= off) ? sh[tid - off] : 0;
            __syncthreads();
            sh[tid] += t;
            __syncthreads();
        }
        int excl = sh[tid] - x + carry;
        if (i < NN) { g_rowptr[i] = excl; g_cursor[i] = excl; }
        __syncthreads();
        if (tid == 1023) carry += sh[1023];
        __syncthreads();
    }
    if (tid == 0) g_rowptr[NN] = carry;   // == EE
}

__global__ void scatter_kernel(const int* __restrict__ rows,
                               const int* __restrict__ cols,
                               const float* __restrict__ vals) {
    int i = blockIdx.x * blockDim.x + threadIdx.x;
    if (i < EE) {
        int r = rows[i];
        int p = atomicAdd(&g_cursor[r], 1);
        g_ccol[p] = cols[i];
        g_cval[p] = vals[i];
    }
}

// ---------------- GEMM1: XW0 = X @ W0  (M x 512) @ (512 x 256) --------------
// 128x128 tile, BK=8, 256 threads, 8x8 per thread.
__global__ void __launch_bounds__(256) gemm1_kernel(const float* __restrict__ A,
                                                    const float* __restrict__ B) {
    const int K = K1, Nc = HD;
    __shared__ float As[8][128];
    __shared__ float Bs[8][128];

    int tid  = threadIdx.x;
    int row0 = blockIdx.y * 128;
    int col0 = blockIdx.x * 128;

    int ar = tid >> 1;             // 0..127
    int ak = (tid & 1) * 4;        // 0 or 4
    int bk = tid >> 5;             // 0..7
    int bc = (tid & 31) * 4;       // 0..124

    int ty = tid >> 4, tx = tid & 15;

    float acc[8][8];
    #pragma unroll
    for (int i = 0; i < 8; i++)
        #pragma unroll
        for (int j = 0; j < 8; j++) acc[i][j] = 0.f;

    float aReg[8], bReg[8];

    for (int kt = 0; kt < K; kt += 8) {
        float4 av = make_float4(0.f, 0.f, 0.f, 0.f);
        int arow = row0 + ar;
        if (arow < NN)
            av = *reinterpret_cast<const float4*>(A + (size_t)arow * K + kt + ak);
        As[ak + 0][ar] = av.x; As[ak + 1][ar] = av.y;
        As[ak + 2][ar] = av.z; As[ak + 3][ar] = av.w;

        float4 bv = *reinterpret_cast<const float4*>(B + (size_t)(kt + bk) * Nc + col0 + bc);
        *reinterpret_cast<float4*>(&Bs[bk][bc]) = bv;
        __syncthreads();

        #pragma unroll
        for (int k = 0; k < 8; k++) {
            *reinterpret_cast<float4*>(aReg)     = *reinterpret_cast<float4*>(&As[k][ty * 8]);
            *reinterpret_cast<float4*>(aReg + 4) = *reinterpret_cast<float4*>(&As[k][ty * 8 + 4]);
            *reinterpret_cast<float4*>(bReg)     = *reinterpret_cast<float4*>(&Bs[k][tx * 8]);
            *reinterpret_cast<float4*>(bReg + 4) = *reinterpret_cast<float4*>(&Bs[k][tx * 8 + 4]);
            #pragma unroll
            for (int i = 0; i < 8; i++)
                #pragma unroll
                for (int j = 0; j < 8; j++)
                    acc[i][j] = fmaf(aReg[i], bReg[j], acc[i][j]);
        }
        __syncthreads();
    }

    #pragma unroll
    for (int i = 0; i < 8; i++) {
        int r = row0 + ty * 8 + i;
        if (r < NN) {
            #pragma unroll
            for (int j = 0; j < 8; j += 4) {
                *reinterpret_cast<float4*>(g_XW0 + (size_t)r * Nc + col0 + tx * 8 + j) =
                    make_float4(acc[i][j], acc[i][j + 1], acc[i][j + 2], acc[i][j + 3]);
            }
        }
    }
}

// ---------------- SpMM1: H1 = relu(A @ XW0), warp per row, no atomics -------
__device__ __forceinline__ void fma4(float4& acc, float v, const float4& a) {
    acc.x = fmaf(v, a.x, acc.x);
    acc.y = fmaf(v, a.y, acc.y);
    acc.z = fmaf(v, a.z, acc.z);
    acc.w = fmaf(v, a.w, acc.w);
}

__global__ void __launch_bounds__(256) spmm1_relu_kernel() {
    int w    = (blockIdx.x * blockDim.x + threadIdx.x) >> 5;
    int lane = threadIdx.x & 31;
    if (w >= NN) return;

    int s = g_rowptr[w], e = g_rowptr[w + 1];
    const float4* Y4 = reinterpret_cast<const float4*>(g_XW0);

    float4 acc0 = make_float4(0.f, 0.f, 0.f, 0.f);
    float4 acc1 = make_float4(0.f, 0.f, 0.f, 0.f);

    int i = s;
    for (; i + 2 <= e; i += 2) {
        int   c0 = g_ccol[i],     c1 = g_ccol[i + 1];
        float v0 = g_cval[i],     v1 = g_cval[i + 1];
        float4 a0 = Y4[(size_t)c0 * 64 + lane];
        float4 b0 = Y4[(size_t)c0 * 64 + 32 + lane];
        float4 a1 = Y4[(size_t)c1 * 64 + lane];
        float4 b1 = Y4[(size_t)c1 * 64 + 32 + lane];
        fma4(acc0, v0, a0); fma4(acc1, v0, b0);
        fma4(acc0, v1, a1); fma4(acc1, v1, b1);
    }
    if (i < e) {
        int c = g_ccol[i]; float v = g_cval[i];
        fma4(acc0, v, Y4[(size_t)c * 64 + lane]);
        fma4(acc1, v, Y4[(size_t)c * 64 + 32 + lane]);
    }

    float4* H4 = reinterpret_cast<float4*>(g_H1);
    H4[(size_t)w * 64 + lane] =
        make_float4(fmaxf(acc0.x, 0.f), fmaxf(acc0.y, 0.f), fmaxf(acc0.z, 0.f), fmaxf(acc0.w, 0.f));
    H4[(size_t)w * 64 + 32 + lane] =
        make_float4(fmaxf(acc1.x, 0.f), fmaxf(acc1.y, 0.f), fmaxf(acc1.z, 0.f), fmaxf(acc1.w, 0.f));
}

// ---------------- GEMM2: H1W1 = H1 @ W1  (M x 256) @ (256 x 64) -------------
// 64x64 tile, BK=16, 256 threads, 4x4 per thread.
__global__ void __launch_bounds__(256) gemm2_kernel(const float* __restrict__ B) {
    const int K = HD, Nc = FD;
    __shared__ float As[16][68];   // pad: row stride 68*4=272B (16B aligned, bank-spread)
    __shared__ float Bs[16][64];

    int tid  = threadIdx.x;
    int row0 = blockIdx.x * 64;

    int ar = tid >> 2;             // 0..63
    int ak = (tid & 3) * 4;        // 0,4,8,12
    int bk = tid >> 4;             // 0..15
    int bc = (tid & 15) * 4;       // 0..60

    int ty = tid >> 4, tx = tid & 15;

    float acc[4][4];
    #pragma unroll
    for (int i = 0; i < 4; i++)
        #pragma unroll
        for (int j = 0; j < 4; j++) acc[i][j] = 0.f;

    for (int kt = 0; kt < K; kt += 16) {
        float4 av = make_float4(0.f, 0.f, 0.f, 0.f);
        int arow = row0 + ar;
        if (arow < NN)
            av = *reinterpret_cast<const float4*>(g_H1 + (size_t)arow * K + kt + ak);
        As[ak + 0][ar] = av.x; As[ak + 1][ar] = av.y;
        As[ak + 2][ar] = av.z; As[ak + 3][ar] = av.w;

        float4 bv = *reinterpret_cast<const float4*>(B + (size_t)(kt + bk) * Nc + bc);
        *reinterpret_cast<float4*>(&Bs[bk][bc]) = bv;
        __syncthreads();

        #pragma unroll
        for (int k = 0; k < 16; k++) {
            float4 a = *reinterpret_cast<float4*>(&As[k][ty * 4]);
            float4 b = *reinterpret_cast<float4*>(&Bs[k][tx * 4]);
            float aa[4] = {a.x, a.y, a.z, a.w};
            float bb[4] = {b.x, b.y, b.z, b.w};
            #pragma unroll
            for (int i = 0; i < 4; i++)
                #pragma unroll
                for (int j = 0; j < 4; j++)
                    acc[i][j] = fmaf(aa[i], bb[j], acc[i][j]);
        }
        __syncthreads();
    }

    #pragma unroll
    for (int i = 0; i < 4; i++) {
        int r = row0 + ty * 4 + i;
        if (r < NN) {
            *reinterpret_cast<float4*>(g_H1W1 + (size_t)r * Nc + tx * 4) =
                make_float4(acc[i][0], acc[i][1], acc[i][2], acc[i][3]);
        }
    }
}

// ---------------- SpMM2 + softmax fused: out = softmax(A @ H1W1) ------------
__global__ void __launch_bounds__(256) spmm2_softmax_kernel(float* __restrict__ out) {
    int w    = (blockIdx.x * blockDim.x + threadIdx.x) >> 5;
    int lane = threadIdx.x & 31;
    if (w >= NN) return;

    int s = g_rowptr[w], e = g_rowptr[w + 1];
    const float2* Y2 = reinterpret_cast<const float2*>(g_H1W1);

    float ax = 0.f, ay = 0.f;
    int i = s;
    for (; i + 2 <= e; i += 2) {
        int   c0 = g_ccol[i],   c1 = g_ccol[i + 1];
        float v0 = g_cval[i],   v1 = g_cval[i + 1];
        float2 y0 = Y2[(size_t)c0 * 32 + lane];
        float2 y1 = Y2[(size_t)c1 * 32 + lane];
        ax = fmaf(v0, y0.x, ax); ay = fmaf(v0, y0.y, ay);
        ax = fmaf(v1, y1.x, ax); ay = fmaf(v1, y1.y, ay);
    }
    if (i < e) {
        int c = g_ccol[i]; float v = g_cval[i];
        float2 y = Y2[(size_t)c * 32 + lane];
        ax = fmaf(v, y.x, ax); ay = fmaf(v, y.y, ay);
    }

    // warp softmax over 64 values (2 per lane)
    float m = fmaxf(ax, ay);
    #pragma unroll
    for (int o = 16; o; o >>= 1) m = fmaxf(m, __shfl_xor_sync(0xffffffffu, m, o));
    float e0 = expf(ax - m), e1 = expf(ay - m);
    float sum = e0 + e1;
    #pragma unroll
    for (int o = 16; o; o >>= 1) sum += __shfl_xor_sync(0xffffffffu, sum, o);
    float inv = 1.f / sum;

    reinterpret_cast<float2*>(out)[(size_t)w * 32 + lane] = make_float2(e0 * inv, e1 * inv);
}

// ---------------- launcher ---------------------------------------------------
extern "C" void kernel_launch(void* const* d_in, const int* in_sizes, int n_in,
                              void* d_out, int out_size) {
    const float* X  = (const float*)d_in[0];
    const int*   er = (const int*)d_in[1];
    const int*   ec = (const int*)d_in[2];
    const float* ev = (const float*)d_in[3];
    const float* W0 = (const float*)d_in[4];
    const float* W1 = (const float*)d_in[5];
    float* out = (float*)d_out;

    // CSR build (counting sort)
    zero_cnt_kernel<<<(NN + 255) / 256, 256>>>();
    hist_kernel<<<(EE + 255) / 256, 256>>>(er);
    scan_kernel<<<1, 1024>>>();
    scatter_kernel<<<(EE + 255) / 256, 256>>>(er, ec, ev);

    // Layer 1
    {
        dim3 grid(HD / 128, (NN + 127) / 128);
        gemm1_kernel<<<grid, 256>>>(X, W0);
    }
    spmm1_relu_kernel<<<(NN * 32 + 255) / 256, 256>>>();

    // Layer 2
    gemm2_kernel<<<(NN + 63) / 64, 256>>>(W1);
    spmm2_softmax_kernel<<<(NN * 32 + 255) / 256, 256>>>(out);
}

// round 2
// speedup vs baseline: 1.5127x; 1.5127x over previous
#include <cuda_runtime.h>
#include <cuda_bf16.h>
#include <cstdint>

// Problem constants (fixed by the dataset)
#define NN 100000      // nodes
#define EE 3200000     // edges
#define K1 512         // X feature dim
#define HD 256         // hidden dim (W0 cols)
#define FD 64          // classes (W1 cols)

// ---------------- scratch (__device__ globals — no runtime allocs) ----------
__device__ float g_XW0[NN * HD];        // X @ W0            (~102 MB)
__device__ float g_H1[NN * HD];         // relu(A @ XW0)     (~102 MB)
__device__ float g_H1W1[NN * FD];       // H1 @ W1           (~25.6 MB)
__device__ int   g_rowptr[NN + 1];
__device__ int   g_cursor[NN];
__device__ int   g_cnt[NN];
__device__ int   g_ccol[EE];
__device__ float g_cval[EE];

// ---------------- packed f32x2 helpers (Blackwell FFMA2) --------------------
__device__ __forceinline__ unsigned long long pk2(float lo, float hi) {
    unsigned long long r;
    asm("mov.b64 %0, {%1, %2};" : "=l"(r) : "f"(lo), "f"(hi));
    return r;
}
__device__ __forceinline__ float2 upk2(unsigned long long v) {
    float2 f;
    asm("mov.b64 {%0, %1}, %2;" : "=f"(f.x), "=f"(f.y) : "l"(v));
    return f;
}
__device__ __forceinline__ unsigned long long ffma2(unsigned long long a,
                                                    unsigned long long b,
                                                    unsigned long long c) {
    unsigned long long d;
    asm("fma.rn.f32x2 %0, %1, %2, %3;" : "=l"(d) : "l"(a), "l"(b), "l"(c));
    return d;
}

// ---------------- CSR build ------------------------------------------------
__global__ void zero_cnt_kernel() {
    int i = blockIdx.x * blockDim.x + threadIdx.x;
    if (i < NN) g_cnt[i] = 0;
}

__global__ void hist_kernel(const int* __restrict__ rows) {
    int i = blockIdx.x * blockDim.x + threadIdx.x;
    if (i < EE) atomicAdd(&g_cnt[rows[i]], 1);
}

// single-block exclusive scan over NN counts -> rowptr & cursor
__global__ void scan_kernel() {
    __shared__ int sh[1024];
    __shared__ int carry;
    int tid = threadIdx.x;
    if (tid == 0) carry = 0;
    __syncthreads();
    for (int base = 0; base < NN; base += 1024) {
        int i = base + tid;
        int x = (i < NN) ? g_cnt[i] : 0;
        sh[tid] = x;
        __syncthreads();
        #pragma unroll
        for (int off = 1; off < 1024; off <<= 1) {
            int t = (tid >= off) ? sh[tid - off] : 0;
            __syncthreads();
            sh[tid] += t;
            __syncthreads();
        }
        int excl = sh[tid] - x + carry;
        if (i < NN) { g_rowptr[i] = excl; g_cursor[i] = excl; }
        __syncthreads();
        if (tid == 1023) carry += sh[1023];
        __syncthreads();
    }
    if (tid == 0) g_rowptr[NN] = carry;   // == EE
}

__global__ void scatter_kernel(const int* __restrict__ rows,
                               const int* __restrict__ cols,
                               const float* __restrict__ vals) {
    int i = blockIdx.x * blockDim.x + threadIdx.x;
    if (i < EE) {
        int r = rows[i];
        int p = atomicAdd(&g_cursor[r], 1);
        g_ccol[p] = cols[i];
        g_cval[p] = vals[i];
    }
}

// ---------------- GEMM1: XW0 = X @ W0  (M x 512) @ (512 x 256) --------------
// 128x128 tile, BK=8, 256 threads, 8x8 per thread, FFMA2 core.
__global__ void __launch_bounds__(256) gemm1_kernel(const float* __restrict__ A,
                                                    const float* __restrict__ B) {
    const int K = K1, Nc = HD;
    __shared__ float As[8][128];
    __shared__ float Bs[8][128];

    int tid  = threadIdx.x;
    int row0 = blockIdx.y * 128;
    int col0 = blockIdx.x * 128;

    int ar = tid >> 1;             // 0..127
    int ak = (tid & 1) * 4;        // 0 or 4
    int bk = tid >> 5;             // 0..7
    int bc = (tid & 31) * 4;       // 0..124

    int ty = tid >> 4, tx = tid & 15;

    // accumulators packed along j: acc2[i][jj] = (acc[i][2jj], acc[i][2jj+1])
    unsigned long long acc2[8][4];
    #pragma unroll
    for (int i = 0; i < 8; i++)
        #pragma unroll
        for (int j = 0; j < 4; j++) acc2[i][j] = 0ull;

    for (int kt = 0; kt < K; kt += 8) {
        float4 av = make_float4(0.f, 0.f, 0.f, 0.f);
        int arow = row0 + ar;
        if (arow < NN)
            av = *reinterpret_cast<const float4*>(A + (size_t)arow * K + kt + ak);
        As[ak + 0][ar] = av.x; As[ak + 1][ar] = av.y;
        As[ak + 2][ar] = av.z; As[ak + 3][ar] = av.w;

        float4 bv = *reinterpret_cast<const float4*>(B + (size_t)(kt + bk) * Nc + col0 + bc);
        *reinterpret_cast<float4*>(&Bs[bk][bc]) = bv;
        __syncthreads();

        #pragma unroll
        for (int k = 0; k < 8; k++) {
            float aR[8];
            *reinterpret_cast<float4*>(aR)     = *reinterpret_cast<float4*>(&As[k][ty * 8]);
            *reinterpret_cast<float4*>(aR + 4) = *reinterpret_cast<float4*>(&As[k][ty * 8 + 4]);
            unsigned long long b2[4];
            *reinterpret_cast<float4*>(&b2[0]) = *reinterpret_cast<float4*>(&Bs[k][tx * 8]);
            *reinterpret_cast<float4*>(&b2[2]) = *reinterpret_cast<float4*>(&Bs[k][tx * 8 + 4]);
            #pragma unroll
            for (int i = 0; i < 8; i++) {
                unsigned long long a2 = pk2(aR[i], aR[i]);
                #pragma unroll
                for (int j = 0; j < 4; j++)
                    acc2[i][j] = ffma2(a2, b2[j], acc2[i][j]);
            }
        }
        __syncthreads();
    }

    #pragma unroll
    for (int i = 0; i < 8; i++) {
        int r = row0 + ty * 8 + i;
        if (r < NN) {
            float2 p0 = upk2(acc2[i][0]), p1 = upk2(acc2[i][1]);
            float2 p2 = upk2(acc2[i][2]), p3 = upk2(acc2[i][3]);
            *reinterpret_cast<float4*>(g_XW0 + (size_t)r * Nc + col0 + tx * 8) =
                make_float4(p0.x, p0.y, p1.x, p1.y);
            *reinterpret_cast<float4*>(g_XW0 + (size_t)r * Nc + col0 + tx * 8 + 4) =
                make_float4(p2.x, p2.y, p3.x, p3.y);
        }
    }
}

// ---------------- SpMM1: H1 = relu(A @ XW0), warp per row, no atomics -------
__device__ __forceinline__ void fma4(float4& acc, float v, const float4& a) {
    acc.x = fmaf(v, a.x, acc.x);
    acc.y = fmaf(v, a.y, acc.y);
    acc.z = fmaf(v, a.z, acc.z);
    acc.w = fmaf(v, a.w, acc.w);
}

__global__ void __launch_bounds__(256) spmm1_relu_kernel() {
    int w    = (blockIdx.x * blockDim.x + threadIdx.x) >> 5;
    int lane = threadIdx.x & 31;
    if (w >= NN) return;

    int s = g_rowptr[w], e = g_rowptr[w + 1];
    const float4* Y4 = reinterpret_cast<const float4*>(g_XW0);

    float4 acc0 = make_float4(0.f, 0.f, 0.f, 0.f);
    float4 acc1 = make_float4(0.f, 0.f, 0.f, 0.f);

    int i = s;
    // unroll 4: 8 independent 16B gathers in flight per lane
    for (; i + 4 <= e; i += 4) {
        int   c0 = g_ccol[i],     c1 = g_ccol[i + 1];
        int   c2 = g_ccol[i + 2], c3 = g_ccol[i + 3];
        float v0 = g_cval[i],     v1 = g_cval[i + 1];
        float v2 = g_cval[i + 2], v3 = g_cval[i + 3];
        float4 a0 = Y4[(size_t)c0 * 64 + lane];
        float4 b0 = Y4[(size_t)c0 * 64 + 32 + lane];
        float4 a1 = Y4[(size_t)c1 * 64 + lane];
        float4 b1 = Y4[(size_t)c1 * 64 + 32 + lane];
        float4 a2 = Y4[(size_t)c2 * 64 + lane];
        float4 b2 = Y4[(size_t)c2 * 64 + 32 + lane];
        float4 a3 = Y4[(size_t)c3 * 64 + lane];
        float4 b3 = Y4[(size_t)c3 * 64 + 32 + lane];
        fma4(acc0, v0, a0); fma4(acc1, v0, b0);
        fma4(acc0, v1, a1); fma4(acc1, v1, b1);
        fma4(acc0, v2, a2); fma4(acc1, v2, b2);
        fma4(acc0, v3, a3); fma4(acc1, v3, b3);
    }
    for (; i < e; i++) {
        int c = g_ccol[i]; float v = g_cval[i];
        fma4(acc0, v, Y4[(size_t)c * 64 + lane]);
        fma4(acc1, v, Y4[(size_t)c * 64 + 32 + lane]);
    }

    float4* H4 = reinterpret_cast<float4*>(g_H1);
    H4[(size_t)w * 64 + lane] =
        make_float4(fmaxf(acc0.x, 0.f), fmaxf(acc0.y, 0.f), fmaxf(acc0.z, 0.f), fmaxf(acc0.w, 0.f));
    H4[(size_t)w * 64 + 32 + lane] =
        make_float4(fmaxf(acc1.x, 0.f), fmaxf(acc1.y, 0.f), fmaxf(acc1.z, 0.f), fmaxf(acc1.w, 0.f));
}

// ---------------- GEMM2: H1W1 = H1 @ W1  (M x 256) @ (256 x 64), FFMA2 ------
__global__ void __launch_bounds__(256) gemm2_kernel(const float* __restrict__ B) {
    const int K = HD, Nc = FD;
    __shared__ float As[16][68];
    __shared__ float Bs[16][64];

    int tid  = threadIdx.x;
    int row0 = blockIdx.x * 64;

    int ar = tid >> 2;             // 0..63
    int ak = (tid & 3) * 4;        // 0,4,8,12
    int bk = tid >> 4;             // 0..15
    int bc = (tid & 15) * 4;       // 0..60

    int ty = tid >> 4, tx = tid & 15;

    unsigned long long acc2[4][2];
    #pragma unroll
    for (int i = 0; i < 4; i++) { acc2[i][0] = 0ull; acc2[i][1] = 0ull; }

    for (int kt = 0; kt < K; kt += 16) {
        float4 av = make_float4(0.f, 0.f, 0.f, 0.f);
        int arow = row0 + ar;
        if (arow < NN)
            av = *reinterpret_cast<const float4*>(g_H1 + (size_t)arow * K + kt + ak);
        As[ak + 0][ar] = av.x; As[ak + 1][ar] = av.y;
        As[ak + 2][ar] = av.z; As[ak + 3][ar] = av.w;

        float4 bv = *reinterpret_cast<const float4*>(B + (size_t)(kt + bk) * Nc + bc);
        *reinterpret_cast<float4*>(&Bs[bk][bc]) = bv;
        __syncthreads();

        #pragma unroll
        for (int k = 0; k < 16; k++) {
            float4 a = *reinterpret_cast<float4*>(&As[k][ty * 4]);
            unsigned long long b2[2];
            *reinterpret_cast<float4*>(&b2[0]) = *reinterpret_cast<float4*>(&Bs[k][tx * 4]);
            float aa[4] = {a.x, a.y, a.z, a.w};
            #pragma unroll
            for (int i = 0; i < 4; i++) {
                unsigned long long a2 = pk2(aa[i], aa[i]);
                acc2[i][0] = ffma2(a2, b2[0], acc2[i][0]);
                acc2[i][1] = ffma2(a2, b2[1], acc2[i][1]);
            }
        }
        __syncthreads();
    }

    #pragma unroll
    for (int i = 0; i < 4; i++) {
        int r = row0 + ty * 4 + i;
        if (r < NN) {
            float2 p0 = upk2(acc2[i][0]), p1 = upk2(acc2[i][1]);
            *reinterpret_cast<float4*>(g_H1W1 + (size_t)r * Nc + tx * 4) =
                make_float4(p0.x, p0.y, p1.x, p1.y);
        }
    }
}

// ---------------- SpMM2 + softmax fused: out = softmax(A @ H1W1) ------------
__global__ void __launch_bounds__(256) spmm2_softmax_kernel(float* __restrict__ out) {
    int w    = (blockIdx.x * blockDim.x + threadIdx.x) >> 5;
    int lane = threadIdx.x & 31;
    if (w >= NN) return;

    int s = g_rowptr[w], e = g_rowptr[w + 1];
    const float2* Y2 = reinterpret_cast<const float2*>(g_H1W1);

    float ax = 0.f, ay = 0.f;
    int i = s;
    for (; i + 4 <= e; i += 4) {
        int   c0 = g_ccol[i],     c1 = g_ccol[i + 1];
        int   c2 = g_ccol[i + 2], c3 = g_ccol[i + 3];
        float v0 = g_cval[i],     v1 = g_cval[i + 1];
        float v2 = g_cval[i + 2], v3 = g_cval[i + 3];
        float2 y0 = Y2[(size_t)c0 * 32 + lane];
        float2 y1 = Y2[(size_t)c1 * 32 + lane];
        float2 y2 = Y2[(size_t)c2 * 32 + lane];
        float2 y3 = Y2[(size_t)c3 * 32 + lane];
        ax = fmaf(v0, y0.x, ax); ay = fmaf(v0, y0.y, ay);
        ax = fmaf(v1, y1.x, ax); ay = fmaf(v1, y1.y, ay);
        ax = fmaf(v2, y2.x, ax); ay = fmaf(v2, y2.y, ay);
        ax = fmaf(v3, y3.x, ax); ay = fmaf(v3, y3.y, ay);
    }
    for (; i < e; i++) {
        int c = g_ccol[i]; float v = g_cval[i];
        float2 y = Y2[(size_t)c * 32 + lane];
        ax = fmaf(v, y.x, ax); ay = fmaf(v, y.y, ay);
    }

    // warp softmax over 64 values (2 per lane)
    float m = fmaxf(ax, ay);
    #pragma unroll
    for (int o = 16; o; o >>= 1) m = fmaxf(m, __shfl_xor_sync(0xffffffffu, m, o));
    float e0 = expf(ax - m), e1 = expf(ay - m);
    float sum = e0 + e1;
    #pragma unroll
    for (int o = 16; o; o >>= 1) sum += __shfl_xor_sync(0xffffffffu, sum, o);
    float inv = 1.f / sum;

    reinterpret_cast<float2*>(out)[(size_t)w * 32 + lane] = make_float2(e0 * inv, e1 * inv);
}

// ---------------- launcher ---------------------------------------------------
extern "C" void kernel_launch(void* const* d_in, const int* in_sizes, int n_in,
                              void* d_out, int out_size) {
    const float* X  = (const float*)d_in[0];
    const int*   er = (const int*)d_in[1];
    const int*   ec = (const int*)d_in[2];
    const float* ev = (const float*)d_in[3];
    const float* W0 = (const float*)d_in[4];
    const float* W1 = (const float*)d_in[5];
    float* out = (float*)d_out;

    // CSR build (counting sort)
    zero_cnt_kernel<<<(NN + 255) / 256, 256>>>();
    hist_kernel<<<(EE + 255) / 256, 256>>>(er);
    scan_kernel<<<1, 1024>>>();
    scatter_kernel<<<(EE + 255) / 256, 256>>>(er, ec, ev);

    // Layer 1
    {
        dim3 grid(HD / 128, (NN + 127) / 128);
        gemm1_kernel<<<grid, 256>>>(X, W0);
    }
    spmm1_relu_kernel<<<(NN * 32 + 255) / 256, 256>>>();

    // Layer 2
    gemm2_kernel<<<(NN + 63) / 64, 256>>>(W1);
    spmm2_softmax_kernel<<<(NN * 32 + 255) / 256, 256>>>(out);
}

// round 4
// speedup vs baseline: 2.1510x; 1.4220x over previous
#include <cuda_runtime.h>
#include <cuda_bf16.h>
#include <cstdint>

#define NN 100000
#define EE 3200000
#define K1 512
#define HD 256
#define FD 64

// ---------------- scratch -----------------------------------------------------
__device__ float g_XW0[NN * HD];
__device__ float g_H1[NN * HD];
__device__ float g_H1W1[NN * FD];
__device__ int   g_rowptr[NN + 1];
__device__ int   g_cursor[NN];
__device__ int   g_cnt[NN];
__device__ int   g_ccol[EE];
__device__ float g_cval[EE];
__device__ __align__(16) __nv_bfloat16 g_W0t_hi[HD * K1];   // W0^T split-high [256][512]
__device__ __align__(16) __nv_bfloat16 g_W0t_lo[HD * K1];   // W0^T split-low

// ---------------- helpers ------------------------------------------------------
__device__ __forceinline__ uint32_t smem_u32(const void* p) {
    uint32_t a;
    asm("{ .reg .u64 t; cvta.to.shared.u64 t, %1; cvt.u32.u64 %0, t; }" : "=r"(a) : "l"(p));
    return a;
}
__device__ __forceinline__ void ldmx4(uint32_t* d, uint32_t addr) {
    asm volatile("ldmatrix.sync.aligned.m8n8.x4.shared.b16 {%0,%1,%2,%3}, [%4];"
                 : "=r"(d[0]), "=r"(d[1]), "=r"(d[2]), "=r"(d[3]) : "r"(addr));
}
__device__ __forceinline__ void mma16816(float* c, const uint32_t* a, uint32_t b0, uint32_t b1) {
    asm volatile("mma.sync.aligned.m16n8k16.row.col.f32.bf16.bf16.f32 "
                 "{%0,%1,%2,%3}, {%4,%5,%6,%7}, {%8,%9}, {%0,%1,%2,%3};"
                 : "+f"(c[0]), "+f"(c[1]), "+f"(c[2]), "+f"(c[3])
                 : "r"(a[0]), "r"(a[1]), "r"(a[2]), "r"(a[3]), "r"(b0), "r"(b1));
}

// ---------------- packed f32x2 (FFMA2) ------------------------------------------
__device__ __forceinline__ unsigned long long pk2(float lo, float hi) {
    unsigned long long r;
    asm("mov.b64 %0, {%1, %2};" : "=l"(r) : "f"(lo), "f"(hi));
    return r;
}
__device__ __forceinline__ float2 upk2(unsigned long long v) {
    float2 f;
    asm("mov.b64 {%0, %1}, %2;" : "=f"(f.x), "=f"(f.y) : "l"(v));
    return f;
}
__device__ __forceinline__ unsigned long long ffma2(unsigned long long a,
                                                    unsigned long long b,
                                                    unsigned long long c) {
    unsigned long long d;
    asm("fma.rn.f32x2 %0, %1, %2, %3;" : "=l"(d) : "l"(a), "l"(b), "l"(c));
    return d;
}

// ---------------- CSR build -----------------------------------------------------
__global__ void zero_cnt_kernel() {
    int i = blockIdx.x * blockDim.x + threadIdx.x;
    if (i < NN) g_cnt[i] = 0;
}
__global__ void hist_kernel(const int* __restrict__ rows) {
    int i = blockIdx.x * blockDim.x + threadIdx.x;
    if (i < EE) atomicAdd(&g_cnt[rows[i]], 1);
}
__global__ void scan_kernel() {
    __shared__ int sh[1024];
    __shared__ int carry;
    int tid = threadIdx.x;
    if (tid == 0) carry = 0;
    __syncthreads();
    for (int base = 0; base < NN; base += 1024) {
        int i = base + tid;
        int x = (i < NN) ? g_cnt[i] : 0;
        sh[tid] = x;
        __syncthreads();
        #pragma unroll
        for (int off = 1; off < 1024; off <<= 1) {
            int t = (tid >= off) ? sh[tid - off] : 0;
            __syncthreads();
            sh[tid] += t;
            __syncthreads();
        }
        int excl = sh[tid] - x + carry;
        if (i < NN) { g_rowptr[i] = excl; g_cursor[i] = excl; }
        __syncthreads();
        if (tid == 1023) carry += sh[1023];
        __syncthreads();
    }
    if (tid == 0) g_rowptr[NN] = carry;
}
__global__ void scatter_kernel(const int* __restrict__ rows,
                               const int* __restrict__ cols,
                               const float* __restrict__ vals) {
    int i = blockIdx.x * blockDim.x + threadIdx.x;
    if (i < EE) {
        int r = rows[i];
        int p = atomicAdd(&g_cursor[r], 1);
        g_ccol[p] = cols[i];
        g_cval[p] = vals[i];
    }
}

// ---------------- W0 transpose + bf16 split --------------------------------------
__global__ void w0_split_kernel(const float* __restrict__ W0) {
    int i = blockIdx.x * blockDim.x + threadIdx.x;   // over K1*HD
    if (i < K1 * HD) {
        int k = i / HD, n = i % HD;
        float v = W0[i];
        __nv_bfloat16 h = __float2bfloat16(v);
        float r = v - __bfloat162float(h);
        g_W0t_hi[n * K1 + k] = h;
        g_W0t_lo[n * K1 + k] = __float2bfloat16(r);
    }
}

// ---------------- GEMM1 via mma.sync (split bf16, 3 products) --------------------
// CTA tile 128(M) x 128(N), K chunks of 32, double-buffered reg-staged SMEM.
// 8 warps: 2(M) x 4(N); warp tile 64x32. SMEM rows stride 40 bf16 (80B) -> ldmatrix
// conflict-free.
#define G1_KC   32
#define G1_NC   (K1 / G1_KC)          // 16 chunks
#define G1_STR  40                    // bf16 per smem row
#define G1_APAD (128 * G1_STR)        // 5120 bf16 = 10240 B per matrix half
#define G1_BUF  (4 * G1_APAD * 2)     // AH,AL,BH,BL per buffer = 40960 B
#define G1_SMEM (2 * G1_BUF)          // 81920 B

__global__ void __launch_bounds__(256) gemm1_mma_kernel(const float* __restrict__ A) {
    extern __shared__ __align__(16) char smem[];
    uint32_t sb = smem_u32(smem);

    int tid  = threadIdx.x;
    int lane = tid & 31;
    int wid  = tid >> 5;
    int wm   = wid >> 2;            // 0..1
    int wn   = wid & 3;             // 0..3
    int row0 = blockIdx.x * 128;
    int col0 = blockIdx.y * 128;

    // staging-load lane mapping
    int a_row = tid >> 3;           // 0..31 (+p*32)
    int a_kc  = (tid & 7) * 4;      // float4 col
    int b_row = tid >> 2;           // 0..63 (+p*64)
    int b_kc  = (tid & 3) * 8;      // uint4 col (8 bf16)

    float4 aS[4];
    uint4  bhS[2], blS[2];

    // ldmatrix source addresses (byte offsets within a buffer half)
    // A frag: row = m + (lane&15), col = ks + 8*(lane>=16)
    uint32_t a_ld_off = (uint32_t)((wm * 64 + (lane & 15)) * G1_STR + ((lane >> 4) << 3)) * 2;
    // B frag: row = n0 + (lane&7) + 8*(lane>=16), col = ks + 8*((lane>>3)&1)
    uint32_t b_ld_off = (uint32_t)((wn * 32 + (lane & 7) + ((lane >> 4) << 3)) * G1_STR
                                   + (((lane >> 3) & 1) << 3)) * 2;

    float acc[4][4][4];
    #pragma unroll
    for (int i = 0; i < 4; i++)
        #pragma unroll
        for (int j = 0; j < 4; j++)
            #pragma unroll
            for (int t = 0; t < 4; t++) acc[i][j][t] = 0.f;

    auto load_stage = [&](int kt) {
        #pragma unroll
        for (int p = 0; p < 4; p++) {
            int r = row0 + a_row + p * 32;
            aS[p] = (r < NN)
                ? *reinterpret_cast<const float4*>(A + (size_t)r * K1 + kt + a_kc)
                : make_float4(0.f, 0.f, 0.f, 0.f);
        }
        #pragma unroll
        for (int p = 0; p < 2; p++) {
            int n = col0 + b_row + p * 64;
            bhS[p] = *reinterpret_cast<const uint4*>(g_W0t_hi + (size_t)n * K1 + kt + b_kc);
            blS[p] = *reinterpret_cast<const uint4*>(g_W0t_lo + (size_t)n * K1 + kt + b_kc);
        }
    };

    auto store_stage = [&](int buf) {
        char* base = smem + buf * G1_BUF;
        #pragma unroll
        for (int p = 0; p < 4; p++) {
            float4 v = aS[p];
            __nv_bfloat162 h01 = __floats2bfloat162_rn(v.x, v.y);
            __nv_bfloat162 h23 = __floats2bfloat162_rn(v.z, v.w);
            float2 f01 = __bfloat1622float2(h01);
            float2 f23 = __bfloat1622float2(h23);
            __nv_bfloat162 l01 = __floats2bfloat162_rn(v.x - f01.x, v.y - f01.y);
            __nv_bfloat162 l23 = __floats2bfloat162_rn(v.z - f23.x, v.w - f23.y);
            uint32_t off = (uint32_t)((a_row + p * 32) * G1_STR + a_kc) * 2;
            *reinterpret_cast<uint2*>(base + off) =
                make_uint2(*(uint32_t*)&h01, *(uint32_t*)&h23);
            *reinterpret_cast<uint2*>(base + 10240 + off) =
                make_uint2(*(uint32_t*)&l01, *(uint32_t*)&l23);
        }
        #pragma unroll
        for (int p = 0; p < 2; p++) {
            uint32_t off = (uint32_t)((b_row + p * 64) * G1_STR + b_kc) * 2;
            *reinterpret_cast<uint4*>(base + 20480 + off) = bhS[p];
            *reinterpret_cast<uint4*>(base + 30720 + off) = blS[p];
        }
    };

    auto compute = [&](int buf) {
        uint32_t ab = sb + buf * G1_BUF;
        #pragma unroll
        for (int ks = 0; ks < 2; ks++) {
            uint32_t kso = (uint32_t)(ks * 16) * 2;
            uint32_t ah[4][4], al[4][4], bh[4][2], bl[4][2];
            #pragma unroll
            for (int i = 0; i < 4; i++) {
                uint32_t ao = ab + a_ld_off + kso + (uint32_t)(i * 16 * G1_STR) * 2;
                ldmx4(ah[i], ao);
                ldmx4(al[i], ao + 10240);
            }
            #pragma unroll
            for (int j2 = 0; j2 < 2; j2++) {
                uint32_t bo = ab + 20480 + b_ld_off + kso + (uint32_t)(j2 * 16 * G1_STR) * 2;
                uint32_t t[4];
                ldmx4(t, bo);
                bh[j2 * 2][0] = t[0]; bh[j2 * 2][1] = t[1];
                bh[j2 * 2 + 1][0] = t[2]; bh[j2 * 2 + 1][1] = t[3];
                ldmx4(t, bo + 10240);
                bl[j2 * 2][0] = t[0]; bl[j2 * 2][1] = t[1];
                bl[j2 * 2 + 1][0] = t[2]; bl[j2 * 2 + 1][1] = t[3];
            }
            #pragma unroll
            for (int i = 0; i < 4; i++)
                #pragma unroll
                for (int j = 0; j < 4; j++) {
                    mma16816(acc[i][j], ah[i], bh[j][0], bh[j][1]);
                    mma16816(acc[i][j], ah[i], bl[j][0], bl[j][1]);
                    mma16816(acc[i][j], al[i], bh[j][0], bh[j][1]);
                }
        }
    };

    // pipeline: stage chunk 0
    load_stage(0);
    store_stage(0);
    __syncthreads();

    for (int c = 0; c < G1_NC; c++) {
        if (c + 1 < G1_NC) load_stage((c + 1) * G1_KC);
        compute(c & 1);
        if (c + 1 < G1_NC) store_stage((c + 1) & 1);
        __syncthreads();
    }

    // epilogue: acc -> g_XW0
    #pragma unroll
    for (int i = 0; i < 4; i++) {
        int r0 = row0 + wm * 64 + i * 16 + (lane >> 2);
        #pragma unroll
        for (int j = 0; j < 4; j++) {
            int cidx = col0 + wn * 32 + j * 8 + (lane & 3) * 2;
            if (r0 < NN)
                *reinterpret_cast<float2*>(g_XW0 + (size_t)r0 * HD + cidx) =
                    make_float2(acc[i][j][0], acc[i][j][1]);
            if (r0 + 8 < NN)
                *reinterpret_cast<float2*>(g_XW0 + (size_t)(r0 + 8) * HD + cidx) =
                    make_float2(acc[i][j][2], acc[i][j][3]);
        }
    }
}

// ---------------- SpMM1: H1 = relu(A @ XW0), warp per row ------------------------
__device__ __forceinline__ void fma4(float4& acc, float v, const float4& a) {
    acc.x = fmaf(v, a.x, acc.x);
    acc.y = fmaf(v, a.y, acc.y);
    acc.z = fmaf(v, a.z, acc.z);
    acc.w = fmaf(v, a.w, acc.w);
}

__global__ void __launch_bounds__(256) spmm1_relu_kernel() {
    int w    = (blockIdx.x * blockDim.x + threadIdx.x) >> 5;
    int lane = threadIdx.x & 31;
    if (w >= NN) return;

    int s = g_rowptr[w], e = g_rowptr[w + 1];
    const float4* Y4 = reinterpret_cast<const float4*>(g_XW0);

    float4 acc0 = make_float4(0.f, 0.f, 0.f, 0.f);
    float4 acc1 = make_float4(0.f, 0.f, 0.f, 0.f);

    int i = s;
    for (; i + 4 <= e; i += 4) {
        int   c0 = g_ccol[i],     c1 = g_ccol[i + 1];
        int   c2 = g_ccol[i + 2], c3 = g_ccol[i + 3];
        float v0 = g_cval[i],     v1 = g_cval[i + 1];
        float v2 = g_cval[i + 2], v3 = g_cval[i + 3];
        float4 a0 = Y4[(size_t)c0 * 64 + lane];
        float4 b0 = Y4[(size_t)c0 * 64 + 32 + lane];
        float4 a1 = Y4[(size_t)c1 * 64 + lane];
        float4 b1 = Y4[(size_t)c1 * 64 + 32 + lane];
        float4 a2 = Y4[(size_t)c2 * 64 + lane];
        float4 b2 = Y4[(size_t)c2 * 64 + 32 + lane];
        float4 a3 = Y4[(size_t)c3 * 64 + lane];
        float4 b3 = Y4[(size_t)c3 * 64 + 32 + lane];
        fma4(acc0, v0, a0); fma4(acc1, v0, b0);
        fma4(acc0, v1, a1); fma4(acc1, v1, b1);
        fma4(acc0, v2, a2); fma4(acc1, v2, b2);
        fma4(acc0, v3, a3); fma4(acc1, v3, b3);
    }
    for (; i < e; i++) {
        int c = g_ccol[i]; float v = g_cval[i];
        fma4(acc0, v, Y4[(size_t)c * 64 + lane]);
        fma4(acc1, v, Y4[(size_t)c * 64 + 32 + lane]);
    }

    float4* H4 = reinterpret_cast<float4*>(g_H1);
    H4[(size_t)w * 64 + lane] =
        make_float4(fmaxf(acc0.x, 0.f), fmaxf(acc0.y, 0.f), fmaxf(acc0.z, 0.f), fmaxf(acc0.w, 0.f));
    H4[(size_t)w * 64 + 32 + lane] =
        make_float4(fmaxf(acc1.x, 0.f), fmaxf(acc1.y, 0.f), fmaxf(acc1.z, 0.f), fmaxf(acc1.w, 0.f));
}

// ---------------- GEMM2: H1W1 = H1 @ W1 (FFMA2) -----------------------------------
__global__ void __launch_bounds__(256) gemm2_kernel(const float* __restrict__ B) {
    const int K = HD, Nc = FD;
    __shared__ float As[16][68];
    __shared__ float Bs[16][64];

    int tid  = threadIdx.x;
    int row0 = blockIdx.x * 64;

    int ar = tid >> 2;
    int ak = (tid & 3) * 4;
    int bk = tid >> 4;
    int bc = (tid & 15) * 4;

    int ty = tid >> 4, tx = tid & 15;

    unsigned long long acc2[4][2];
    #pragma unroll
    for (int i = 0; i < 4; i++) { acc2[i][0] = 0ull; acc2[i][1] = 0ull; }

    for (int kt = 0; kt < K; kt += 16) {
        float4 av = make_float4(0.f, 0.f, 0.f, 0.f);
        int arow = row0 + ar;
        if (arow < NN)
            av = *reinterpret_cast<const float4*>(g_H1 + (size_t)arow * K + kt + ak);
        As[ak + 0][ar] = av.x; As[ak + 1][ar] = av.y;
        As[ak + 2][ar] = av.z; As[ak + 3][ar] = av.w;

        float4 bv = *reinterpret_cast<const float4*>(B + (size_t)(kt + bk) * Nc + bc);
        *reinterpret_cast<float4*>(&Bs[bk][bc]) = bv;
        __syncthreads();

        #pragma unroll
        for (int k = 0; k < 16; k++) {
            float4 a = *reinterpret_cast<float4*>(&As[k][ty * 4]);
            unsigned long long b2[2];
            *reinterpret_cast<float4*>(&b2[0]) = *reinterpret_cast<float4*>(&Bs[k][tx * 4]);
            float aa[4] = {a.x, a.y, a.z, a.w};
            #pragma unroll
            for (int i = 0; i < 4; i++) {
                unsigned long long a2 = pk2(aa[i], aa[i]);
                acc2[i][0] = ffma2(a2, b2[0], acc2[i][0]);
                acc2[i][1] = ffma2(a2, b2[1], acc2[i][1]);
            }
        }
        __syncthreads();
    }

    #pragma unroll
    for (int i = 0; i < 4; i++) {
        int r = row0 + ty * 4 + i;
        if (r < NN) {
            float2 p0 = upk2(acc2[i][0]), p1 = upk2(acc2[i][1]);
            *reinterpret_cast<float4*>(g_H1W1 + (size_t)r * Nc + tx * 4) =
                make_float4(p0.x, p0.y, p1.x, p1.y);
        }
    }
}

// ---------------- SpMM2 + softmax -------------------------------------------------
__global__ void __launch_bounds__(256) spmm2_softmax_kernel(float* __restrict__ out) {
    int w    = (blockIdx.x * blockDim.x + threadIdx.x) >> 5;
    int lane = threadIdx.x & 31;
    if (w >= NN) return;

    int s = g_rowptr[w], e = g_rowptr[w + 1];
    const float2* Y2 = reinterpret_cast<const float2*>(g_H1W1);

    float ax = 0.f, ay = 0.f;
    int i = s;
    for (; i + 4 <= e; i += 4) {
        int   c0 = g_ccol[i],     c1 = g_ccol[i + 1];
        int   c2 = g_ccol[i + 2], c3 = g_ccol[i + 3];
        float v0 = g_cval[i],     v1 = g_cval[i + 1];
        float v2 = g_cval[i + 2], v3 = g_cval[i + 3];
        float2 y0 = Y2[(size_t)c0 * 32 + lane];
        float2 y1 = Y2[(size_t)c1 * 32 + lane];
        float2 y2 = Y2[(size_t)c2 * 32 + lane];
        float2 y3 = Y2[(size_t)c3 * 32 + lane];
        ax = fmaf(v0, y0.x, ax); ay = fmaf(v0, y0.y, ay);
        ax = fmaf(v1, y1.x, ax); ay = fmaf(v1, y1.y, ay);
        ax = fmaf(v2, y2.x, ax); ay = fmaf(v2, y2.y, ay);
        ax = fmaf(v3, y3.x, ax); ay = fmaf(v3, y3.y, ay);
    }
    for (; i < e; i++) {
        int c = g_ccol[i]; float v = g_cval[i];
        float2 y = Y2[(size_t)c * 32 + lane];
        ax = fmaf(v, y.x, ax); ay = fmaf(v, y.y, ay);
    }

    float m = fmaxf(ax, ay);
    #pragma unroll
    for (int o = 16; o; o >>= 1) m = fmaxf(m, __shfl_xor_sync(0xffffffffu, m, o));
    float e0 = expf(ax - m), e1 = expf(ay - m);
    float sum = e0 + e1;
    #pragma unroll
    for (int o = 16; o; o >>= 1) sum += __shfl_xor_sync(0xffffffffu, sum, o);
    float inv = 1.f / sum;

    reinterpret_cast<float2*>(out)[(size_t)w * 32 + lane] = make_float2(e0 * inv, e1 * inv);
}

// ---------------- launcher ----------------------------------------------------------
extern "C" void kernel_launch(void* const* d_in, const int* in_sizes, int n_in,
                              void* d_out, int out_size) {
    const float* X  = (const float*)d_in[0];
    const int*   er = (const int*)d_in[1];
    const int*   ec = (const int*)d_in[2];
    const float* ev = (const float*)d_in[3];
    const float* W0 = (const float*)d_in[4];
    const float* W1 = (const float*)d_in[5];
    float* out = (float*)d_out;

    static bool attr_done = false;
    if (!attr_done) {
        cudaFuncSetAttribute(gemm1_mma_kernel,
                             cudaFuncAttributeMaxDynamicSharedMemorySize, G1_SMEM);
        attr_done = true;
    }

    // CSR build
    zero_cnt_kernel<<<(NN + 255) / 256, 256>>>();
    hist_kernel<<<(EE + 255) / 256, 256>>>(er);
    scan_kernel<<<1, 1024>>>();
    scatter_kernel<<<(EE + 255) / 256, 256>>>(er, ec, ev);

    // W0 prep + Layer 1
    w0_split_kernel<<<(K1 * HD + 255) / 256, 256>>>(W0);
    {
        dim3 grid((NN + 127) / 128, HD / 128);
        gemm1_mma_kernel<<<grid, 256, G1_SMEM>>>(X);
    }
    spmm1_relu_kernel<<<(NN * 32 + 255) / 256, 256>>>();

    // Layer 2
    gemm2_kernel<<<(NN + 63) / 64, 256>>>(W1);
    spmm2_softmax_kernel<<<(NN * 32 + 255) / 256, 256>>>(out);
}

// round 6
// speedup vs baseline: 2.4192x; 1.1247x over previous
#include <cuda_runtime.h>
#include <cuda_bf16.h>
#include <cuda_fp16.h>
#include <cstdint>

#define NN 100000
#define EE 3200000
#define K1 512
#define HD 256
#define FD 64

// ---------------- scratch -----------------------------------------------------
__device__ __align__(16) __half g_XW0h[NN * HD];   // X @ W0 in fp16 (51 MB)
__device__ __align__(16) float g_H1[NN * HD];      // relu(A @ XW0) fp32
__device__ __align__(16) float g_H1W1[NN * FD];
__device__ int   g_rowptr[NN + 1];
__device__ int   g_cursor[NN];
__device__ int   g_cnt[NN];
__device__ int   g_ccol[EE];
__device__ float g_cval[EE];
__device__ __align__(16) __nv_bfloat16 g_W0t_hi[HD * K1];  // W0^T split [256][512]
__device__ __align__(16) __nv_bfloat16 g_W0t_lo[HD * K1];

// ---------------- helpers ------------------------------------------------------
__device__ __forceinline__ uint32_t smem_u32(const void* p) {
    uint32_t a;
    asm("{ .reg .u64 t; cvta.to.shared.u64 t, %1; cvt.u32.u64 %0, t; }" : "=r"(a) : "l"(p));
    return a;
}
__device__ __forceinline__ void ldmx4(uint32_t* d, uint32_t addr) {
    asm volatile("ldmatrix.sync.aligned.m8n8.x4.shared.b16 {%0,%1,%2,%3}, [%4];"
                 : "=r"(d[0]), "=r"(d[1]), "=r"(d[2]), "=r"(d[3]) : "r"(addr));
}
__device__ __forceinline__ void mma16816(float* c, const uint32_t* a, uint32_t b0, uint32_t b1) {
    asm volatile("mma.sync.aligned.m16n8k16.row.col.f32.bf16.bf16.f32 "
                 "{%0,%1,%2,%3}, {%4,%5,%6,%7}, {%8,%9}, {%0,%1,%2,%3};"
                 : "+f"(c[0]), "+f"(c[1]), "+f"(c[2]), "+f"(c[3])
                 : "r"(a[0]), "r"(a[1]), "r"(a[2]), "r"(a[3]), "r"(b0), "r"(b1));
}

// ---------------- packed f32x2 (FFMA2) ------------------------------------------
__device__ __forceinline__ unsigned long long pk2(float lo, float hi) {
    unsigned long long r;
    asm("mov.b64 %0, {%1, %2};" : "=l"(r) : "f"(lo), "f"(hi));
    return r;
}
__device__ __forceinline__ float2 upk2(unsigned long long v) {
    float2 f;
    asm("mov.b64 {%0, %1}, %2;" : "=f"(f.x), "=f"(f.y) : "l"(v));
    return f;
}
__device__ __forceinline__ unsigned long long ffma2(unsigned long long a,
                                                    unsigned long long b,
                                                    unsigned long long c) {
    unsigned long long d;
    asm("fma.rn.f32x2 %0, %1, %2, %3;" : "=l"(d) : "l"(a), "l"(b), "l"(c));
    return d;
}

// ---------------- CSR build -----------------------------------------------------
__global__ void zero_cnt_kernel() {
    int i = blockIdx.x * blockDim.x + threadIdx.x;
    if (i < NN) g_cnt[i] = 0;
}
__global__ void hist_kernel(const int* __restrict__ rows) {
    int i = blockIdx.x * blockDim.x + threadIdx.x;
    if (i < EE) atomicAdd(&g_cnt[rows[i]], 1);
}
__global__ void scan_kernel() {
    __shared__ int sh[1024];
    __shared__ int carry;
    int tid = threadIdx.x;
    if (tid == 0) carry = 0;
    __syncthreads();
    for (int base = 0; base < NN; base += 1024) {
        int i = base + tid;
        int x = (i < NN) ? g_cnt[i] : 0;
        sh[tid] = x;
        __syncthreads();
        #pragma unroll
        for (int off = 1; off < 1024; off <<= 1) {
            int t = (tid >= off) ? sh[tid - off] : 0;
            __syncthreads();
            sh[tid] += t;
            __syncthreads();
        }
        int excl = sh[tid] - x + carry;
        if (i < NN) { g_rowptr[i] = excl; g_cursor[i] = excl; }
        __syncthreads();
        if (tid == 1023) carry += sh[1023];
        __syncthreads();
    }
    if (tid == 0) g_rowptr[NN] = carry;
}
__global__ void scatter_kernel(const int* __restrict__ rows,
                               const int* __restrict__ cols,
                               const float* __restrict__ vals) {
    int i = blockIdx.x * blockDim.x + threadIdx.x;
    if (i < EE) {
        int r = rows[i];
        int p = atomicAdd(&g_cursor[r], 1);
        g_ccol[p] = cols[i];
        g_cval[p] = vals[i];
    }
}

// ---------------- W0 transpose + bf16 split --------------------------------------
__global__ void w0_split_kernel(const float* __restrict__ W0) {
    int i = blockIdx.x * blockDim.x + threadIdx.x;   // over K1*HD
    if (i < K1 * HD) {
        int k = i / HD, n = i % HD;
        float v = W0[i];
        __nv_bfloat16 h = __float2bfloat16(v);
        g_W0t_hi[n * K1 + k] = h;
        g_W0t_lo[n * K1 + k] = __float2bfloat16(v - __bfloat162float(h));
    }
}

// ---------------- GEMM1 via mma.sync (split bf16, 3 products), fp16 out -----------
#define G1_KC   32
#define G1_NC   (K1 / G1_KC)
#define G1_STR  40
#define G1_BUF  40960
#define G1_SMEM (2 * G1_BUF)

__global__ void __launch_bounds__(256) gemm1_mma_kernel(const float* __restrict__ A) {
    extern __shared__ __align__(16) char smem[];
    uint32_t sb = smem_u32(smem);

    int tid  = threadIdx.x;
    int lane = tid & 31;
    int wid  = tid >> 5;
    int wm   = wid >> 2;
    int wn   = wid & 3;
    int row0 = blockIdx.x * 128;
    int col0 = blockIdx.y * 128;

    int a_row = tid >> 3;
    int a_kc  = (tid & 7) * 4;
    int b_row = tid >> 2;
    int b_kc  = (tid & 3) * 8;

    float4 aS[4];
    uint4  bhS[2], blS[2];

    uint32_t a_ld_off = (uint32_t)((wm * 64 + (lane & 15)) * G1_STR + ((lane >> 4) << 3)) * 2;
    uint32_t b_ld_off = (uint32_t)((wn * 32 + (lane & 7) + ((lane >> 4) << 3)) * G1_STR
                                   + (((lane >> 3) & 1) << 3)) * 2;

    float acc[4][4][4];
    #pragma unroll
    for (int i = 0; i < 4; i++)
        #pragma unroll
        for (int j = 0; j < 4; j++)
            #pragma unroll
            for (int t = 0; t < 4; t++) acc[i][j][t] = 0.f;

    auto load_stage = [&](int kt) {
        #pragma unroll
        for (int p = 0; p < 4; p++) {
            int r = row0 + a_row + p * 32;
            aS[p] = (r < NN)
                ? *reinterpret_cast<const float4*>(A + (size_t)r * K1 + kt + a_kc)
                : make_float4(0.f, 0.f, 0.f, 0.f);
        }
        #pragma unroll
        for (int p = 0; p < 2; p++) {
            int n = col0 + b_row + p * 64;
            bhS[p] = *reinterpret_cast<const uint4*>(g_W0t_hi + (size_t)n * K1 + kt + b_kc);
            blS[p] = *reinterpret_cast<const uint4*>(g_W0t_lo + (size_t)n * K1 + kt + b_kc);
        }
    };

    auto store_stage = [&](int buf) {
        char* base = smem + buf * G1_BUF;
        #pragma unroll
        for (int p = 0; p < 4; p++) {
            float4 v = aS[p];
            __nv_bfloat162 h01 = __floats2bfloat162_rn(v.x, v.y);
            __nv_bfloat162 h23 = __floats2bfloat162_rn(v.z, v.w);
            float2 f01 = __bfloat1622float2(h01);
            float2 f23 = __bfloat1622float2(h23);
            __nv_bfloat162 l01 = __floats2bfloat162_rn(v.x - f01.x, v.y - f01.y);
            __nv_bfloat162 l23 = __floats2bfloat162_rn(v.z - f23.x, v.w - f23.y);
            uint32_t off = (uint32_t)((a_row + p * 32) * G1_STR + a_kc) * 2;
            *reinterpret_cast<uint2*>(base + off) =
                make_uint2(*(uint32_t*)&h01, *(uint32_t*)&h23);
            *reinterpret_cast<uint2*>(base + 10240 + off) =
                make_uint2(*(uint32_t*)&l01, *(uint32_t*)&l23);
        }
        #pragma unroll
        for (int p = 0; p < 2; p++) {
            uint32_t off = (uint32_t)((b_row + p * 64) * G1_STR + b_kc) * 2;
            *reinterpret_cast<uint4*>(base + 20480 + off) = bhS[p];
            *reinterpret_cast<uint4*>(base + 30720 + off) = blS[p];
        }
    };

    auto compute = [&](int buf) {
        uint32_t ab = sb + buf * G1_BUF;
        #pragma unroll
        for (int ks = 0; ks < 2; ks++) {
            uint32_t kso = (uint32_t)(ks * 16) * 2;
            uint32_t ah[4][4], al[4][4], bh[4][2], bl[4][2];
            #pragma unroll
            for (int i = 0; i < 4; i++) {
                uint32_t ao = ab + a_ld_off + kso + (uint32_t)(i * 16 * G1_STR) * 2;
                ldmx4(ah[i], ao);
                ldmx4(al[i], ao + 10240);
            }
            #pragma unroll
            for (int j2 = 0; j2 < 2; j2++) {
                uint32_t bo = ab + 20480 + b_ld_off + kso + (uint32_t)(j2 * 16 * G1_STR) * 2;
                uint32_t t[4];
                ldmx4(t, bo);
                bh[j2 * 2][0] = t[0]; bh[j2 * 2][1] = t[1];
                bh[j2 * 2 + 1][0] = t[2]; bh[j2 * 2 + 1][1] = t[3];
                ldmx4(t, bo + 10240);
                bl[j2 * 2][0] = t[0]; bl[j2 * 2][1] = t[1];
                bl[j2 * 2 + 1][0] = t[2]; bl[j2 * 2 + 1][1] = t[3];
            }
            #pragma unroll
            for (int i = 0; i < 4; i++)
                #pragma unroll
                for (int j = 0; j < 4; j++) {
                    mma16816(acc[i][j], ah[i], bh[j][0], bh[j][1]);
                    mma16816(acc[i][j], ah[i], bl[j][0], bl[j][1]);
                    mma16816(acc[i][j], al[i], bh[j][0], bh[j][1]);
                }
        }
    };

    load_stage(0);
    store_stage(0);
    __syncthreads();

    for (int c = 0; c < G1_NC; c++) {
        if (c + 1 < G1_NC) load_stage((c + 1) * G1_KC);
        compute(c & 1);
        if (c + 1 < G1_NC) store_stage((c + 1) & 1);
        __syncthreads();
    }

    // epilogue -> fp16
    #pragma unroll
    for (int i = 0; i < 4; i++) {
        int r0 = row0 + wm * 64 + i * 16 + (lane >> 2);
        #pragma unroll
        for (int j = 0; j < 4; j++) {
            int cidx = col0 + wn * 32 + j * 8 + (lane & 3) * 2;
            if (r0 < NN)
                *reinterpret_cast<__half2*>(g_XW0h + (size_t)r0 * HD + cidx) =
                    __floats2half2_rn(acc[i][j][0], acc[i][j][1]);
            if (r0 + 8 < NN)
                *reinterpret_cast<__half2*>(g_XW0h + (size_t)(r0 + 8) * HD + cidx) =
                    __floats2half2_rn(acc[i][j][2], acc[i][j][3]);
        }
    }
}

// ---------------- SpMM1: H1 = relu(A @ XW0h) -> fp32, warp per row ----------------
__device__ __forceinline__ void fmah8(float* acc, float v, const uint4& q) {
    const __half2* h = reinterpret_cast<const __half2*>(&q);
    #pragma unroll
    for (int t = 0; t < 4; t++) {
        float2 f = __half22float2(h[t]);
        acc[2 * t]     = fmaf(v, f.x, acc[2 * t]);
        acc[2 * t + 1] = fmaf(v, f.y, acc[2 * t + 1]);
    }
}

__global__ void __launch_bounds__(256) spmm1_relu_kernel() {
    int w    = (blockIdx.x * blockDim.x + threadIdx.x) >> 5;
    int lane = threadIdx.x & 31;
    if (w >= NN) return;

    int s = g_rowptr[w], e = g_rowptr[w + 1];
    const uint4* Yh = reinterpret_cast<const uint4*>(g_XW0h);  // 32 uint4 per row

    float acc[8];
    #pragma unroll
    for (int t = 0; t < 8; t++) acc[t] = 0.f;

    int i = s;
    for (; i + 4 <= e; i += 4) {
        int   c0 = g_ccol[i],     c1 = g_ccol[i + 1];
        int   c2 = g_ccol[i + 2], c3 = g_ccol[i + 3];
        float v0 = g_cval[i],     v1 = g_cval[i + 1];
        float v2 = g_cval[i + 2], v3 = g_cval[i + 3];
        uint4 q0 = Yh[(size_t)c0 * 32 + lane];
        uint4 q1 = Yh[(size_t)c1 * 32 + lane];
        uint4 q2 = Yh[(size_t)c2 * 32 + lane];
        uint4 q3 = Yh[(size_t)c3 * 32 + lane];
        fmah8(acc, v0, q0);
        fmah8(acc, v1, q1);
        fmah8(acc, v2, q2);
        fmah8(acc, v3, q3);
    }
    for (; i < e; i++) {
        int c = g_ccol[i]; float v = g_cval[i];
        uint4 q = Yh[(size_t)c * 32 + lane];
        fmah8(acc, v, q);
    }

    // relu -> fp32 H1, 8 contiguous features at lane*8
    float* dst = g_H1 + (size_t)w * HD + lane * 8;
    *reinterpret_cast<float4*>(dst) =
        make_float4(fmaxf(acc[0], 0.f), fmaxf(acc[1], 0.f),
                    fmaxf(acc[2], 0.f), fmaxf(acc[3], 0.f));
    *reinterpret_cast<float4*>(dst + 4) =
        make_float4(fmaxf(acc[4], 0.f), fmaxf(acc[5], 0.f),
                    fmaxf(acc[6], 0.f), fmaxf(acc[7], 0.f));
}

// ---------------- GEMM2: H1W1 = H1 @ W1 (FFMA2, known good) ------------------------
__global__ void __launch_bounds__(256) gemm2_kernel(const float* __restrict__ B) {
    const int K = HD, Nc = FD;
    __shared__ float As[16][68];
    __shared__ float Bs[16][64];

    int tid  = threadIdx.x;
    int row0 = blockIdx.x * 64;

    int ar = tid >> 2;
    int ak = (tid & 3) * 4;
    int bk = tid >> 4;
    int bc = (tid & 15) * 4;

    int ty = tid >> 4, tx = tid & 15;

    unsigned long long acc2[4][2];
    #pragma unroll
    for (int i = 0; i < 4; i++) { acc2[i][0] = 0ull; acc2[i][1] = 0ull; }

    for (int kt = 0; kt < K; kt += 16) {
        float4 av = make_float4(0.f, 0.f, 0.f, 0.f);
        int arow = row0 + ar;
        if (arow < NN)
            av = *reinterpret_cast<const float4*>(g_H1 + (size_t)arow * K + kt + ak);
        As[ak + 0][ar] = av.x; As[ak + 1][ar] = av.y;
        As[ak + 2][ar] = av.z; As[ak + 3][ar] = av.w;

        float4 bv = *reinterpret_cast<const float4*>(B + (size_t)(kt + bk) * Nc + bc);
        *reinterpret_cast<float4*>(&Bs[bk][bc]) = bv;
        __syncthreads();

        #pragma unroll
        for (int k = 0; k < 16; k++) {
            float4 a = *reinterpret_cast<float4*>(&As[k][ty * 4]);
            unsigned long long b2[2];
            *reinterpret_cast<float4*>(&b2[0]) = *reinterpret_cast<float4*>(&Bs[k][tx * 4]);
            float aa[4] = {a.x, a.y, a.z, a.w};
            #pragma unroll
            for (int i = 0; i < 4; i++) {
                unsigned long long a2 = pk2(aa[i], aa[i]);
                acc2[i][0] = ffma2(a2, b2[0], acc2[i][0]);
                acc2[i][1] = ffma2(a2, b2[1], acc2[i][1]);
            }
        }
        __syncthreads();
    }

    #pragma unroll
    for (int i = 0; i < 4; i++) {
        int r = row0 + ty * 4 + i;
        if (r < NN) {
            float2 p0 = upk2(acc2[i][0]), p1 = upk2(acc2[i][1]);
            *reinterpret_cast<float4*>(g_H1W1 + (size_t)r * Nc + tx * 4) =
                make_float4(p0.x, p0.y, p1.x, p1.y);
        }
    }
}

// ---------------- SpMM2 + softmax -------------------------------------------------
__global__ void __launch_bounds__(256) spmm2_softmax_kernel(float* __restrict__ out) {
    int w    = (blockIdx.x * blockDim.x + threadIdx.x) >> 5;
    int lane = threadIdx.x & 31;
    if (w >= NN) return;

    int s = g_rowptr[w], e = g_rowptr[w + 1];
    const float2* Y2 = reinterpret_cast<const float2*>(g_H1W1);

    float ax = 0.f, ay = 0.f;
    int i = s;
    for (; i + 4 <= e; i += 4) {
        int   c0 = g_ccol[i],     c1 = g_ccol[i + 1];
        int   c2 = g_ccol[i + 2], c3 = g_ccol[i + 3];
        float v0 = g_cval[i],     v1 = g_cval[i + 1];
        float v2 = g_cval[i + 2], v3 = g_cval[i + 3];
        float2 y0 = Y2[(size_t)c0 * 32 + lane];
        float2 y1 = Y2[(size_t)c1 * 32 + lane];
        float2 y2 = Y2[(size_t)c2 * 32 + lane];
        float2 y3 = Y2[(size_t)c3 * 32 + lane];
        ax = fmaf(v0, y0.x, ax); ay = fmaf(v0, y0.y, ay);
        ax = fmaf(v1, y1.x, ax); ay = fmaf(v1, y1.y, ay);
        ax = fmaf(v2, y2.x, ax); ay = fmaf(v2, y2.y, ay);
        ax = fmaf(v3, y3.x, ax); ay = fmaf(v3, y3.y, ay);
    }
    for (; i < e; i++) {
        int c = g_ccol[i]; float v = g_cval[i];
        float2 y = Y2[(size_t)c * 32 + lane];
        ax = fmaf(v, y.x, ax); ay = fmaf(v, y.y, ay);
    }

    float m = fmaxf(ax, ay);
    #pragma unroll
    for (int o = 16; o; o >>= 1) m = fmaxf(m, __shfl_xor_sync(0xffffffffu, m, o));
    float e0 = expf(ax - m), e1 = expf(ay - m);
    float sum = e0 + e1;
    #pragma unroll
    for (int o = 16; o; o >>= 1) sum += __shfl_xor_sync(0xffffffffu, sum, o);
    float inv = 1.f / sum;

    reinterpret_cast<float2*>(out)[(size_t)w * 32 + lane] = make_float2(e0 * inv, e1 * inv);
}

// ---------------- launcher ----------------------------------------------------------
extern "C" void kernel_launch(void* const* d_in, const int* in_sizes, int n_in,
                              void* d_out, int out_size) {
    const float* X  = (const float*)d_in[0];
    const int*   er = (const int*)d_in[1];
    const int*   ec = (const int*)d_in[2];
    const float* ev = (const float*)d_in[3];
    const float* W0 = (const float*)d_in[4];
    const float* W1 = (const float*)d_in[5];
    float* out = (float*)d_out;

    static bool attr_done = false;
    if (!attr_done) {
        cudaFuncSetAttribute(gemm1_mma_kernel,
                             cudaFuncAttributeMaxDynamicSharedMemorySize, G1_SMEM);
        attr_done = true;
    }

    // CSR build
    zero_cnt_kernel<<<(NN + 255) / 256, 256>>>();
    hist_kernel<<<(EE + 255) / 256, 256>>>(er);
    scan_kernel<<<1, 1024>>>();
    scatter_kernel<<<(EE + 255) / 256, 256>>>(er, ec, ev);

    // W0 prep + Layer 1
    w0_split_kernel<<<(K1 * HD + 255) / 256, 256>>>(W0);
    {
        dim3 grid((NN + 127) / 128, HD / 128);
        gemm1_mma_kernel<<<grid, 256, G1_SMEM>>>(X);
    }
    spmm1_relu_kernel<<<(NN * 32 + 255) / 256, 256>>>();

    // Layer 2
    gemm2_kernel<<<(NN + 63) / 64, 256>>>(W1);
    spmm2_softmax_kernel<<<(NN * 32 + 255) / 256, 256>>>(out);
}

// round 7
// speedup vs baseline: 2.9195x; 1.2068x over previous
#include <cuda_runtime.h>
#include <cuda_bf16.h>
#include <cuda_fp16.h>
#include <cstdint>

#define NN 100000
#define EE 3200000
#define K1 512
#define HD 256
#define FD 64

// ---------------- scratch -----------------------------------------------------
__device__ __align__(16) __half g_XW0h[NN * HD];   // X @ W0 in fp16 (51 MB)
__device__ __align__(16) float g_H1[NN * HD];      // relu(A @ XW0) fp32
__device__ __align__(16) float g_H1W1[NN * FD];
__device__ int   g_rowptr[NN + 1];
__device__ int   g_cursor[NN];
__device__ int   g_cnt[NN];
__device__ __align__(16) int2 g_cedge[EE];         // (col, valbits) fused
__device__ __align__(16) __half g_W0t_h[HD * K1];  // W0^T fp16 [256][512]

// ---------------- helpers ------------------------------------------------------
__device__ __forceinline__ uint32_t smem_u32(const void* p) {
    uint32_t a;
    asm("{ .reg .u64 t; cvta.to.shared.u64 t, %1; cvt.u32.u64 %0, t; }" : "=r"(a) : "l"(p));
    return a;
}
__device__ __forceinline__ void ldmx4(uint32_t* d, uint32_t addr) {
    asm volatile("ldmatrix.sync.aligned.m8n8.x4.shared.b16 {%0,%1,%2,%3}, [%4];"
                 : "=r"(d[0]), "=r"(d[1]), "=r"(d[2]), "=r"(d[3]) : "r"(addr));
}
__device__ __forceinline__ void mma16816h(float* c, const uint32_t* a, uint32_t b0, uint32_t b1) {
    asm volatile("mma.sync.aligned.m16n8k16.row.col.f32.f16.f16.f32 "
                 "{%0,%1,%2,%3}, {%4,%5,%6,%7}, {%8,%9}, {%0,%1,%2,%3};"
                 : "+f"(c[0]), "+f"(c[1]), "+f"(c[2]), "+f"(c[3])
                 : "r"(a[0]), "r"(a[1]), "r"(a[2]), "r"(a[3]), "r"(b0), "r"(b1));
}

// ---------------- packed f32x2 (FFMA2) ------------------------------------------
__device__ __forceinline__ unsigned long long pk2(float lo, float hi) {
    unsigned long long r;
    asm("mov.b64 %0, {%1, %2};" : "=l"(r) : "f"(lo), "f"(hi));
    return r;
}
__device__ __forceinline__ float2 upk2(unsigned long long v) {
    float2 f;
    asm("mov.b64 {%0, %1}, %2;" : "=f"(f.x), "=f"(f.y) : "l"(v));
    return f;
}
__device__ __forceinline__ unsigned long long ffma2(unsigned long long a,
                                                    unsigned long long b,
                                                    unsigned long long c) {
    unsigned long long d;
    asm("fma.rn.f32x2 %0, %1, %2, %3;" : "=l"(d) : "l"(a), "l"(b), "l"(c));
    return d;
}

// ---------------- CSR build -----------------------------------------------------
__global__ void zero_cnt_kernel() {
    int i = blockIdx.x * blockDim.x + threadIdx.x;
    if (i < NN) g_cnt[i] = 0;
}
__global__ void hist_kernel(const int4* __restrict__ rows4) {
    int i = blockIdx.x * blockDim.x + threadIdx.x;
    if (i < EE / 4) {
        int4 r = rows4[i];
        atomicAdd(&g_cnt[r.x], 1);
        atomicAdd(&g_cnt[r.y], 1);
        atomicAdd(&g_cnt[r.z], 1);
        atomicAdd(&g_cnt[r.w], 1);
    }
}
// 1024 threads, serial-per-thread + warp-shfl block scan
__global__ void __launch_bounds__(1024) scan_kernel() {
    __shared__ int wsum[32];
    int tid = threadIdx.x;
    const int PER = 98;                      // 1024*98 >= NN
    int base = tid * PER;
    int s = 0;
    for (int j = 0; j < PER; j++) {
        int i = base + j;
        if (i < NN) s += g_cnt[i];
    }
    int lane = tid & 31, wid = tid >> 5;
    int x = s;
    #pragma unroll
    for (int o = 1; o < 32; o <<= 1) {
        int t = __shfl_up_sync(0xffffffffu, x, o);
        if (lane >= o) x += t;
    }
    if (lane == 31) wsum[wid] = x;
    __syncthreads();
    if (wid == 0) {
        int w = wsum[lane];
        #pragma unroll
        for (int o = 1; o < 32; o <<= 1) {
            int t = __shfl_up_sync(0xffffffffu, w, o);
            if (lane >= o) w += t;
        }
        wsum[lane] = w;
    }
    __syncthreads();
    int excl = x - s + (wid > 0 ? wsum[wid - 1] : 0);
    int run = excl;
    for (int j = 0; j < PER; j++) {
        int i = base + j;
        if (i < NN) {
            g_rowptr[i] = run;
            g_cursor[i] = run;
            run += g_cnt[i];
        }
    }
    if (tid == 1023) g_rowptr[NN] = run;
}
__global__ void scatter_kernel(const int* __restrict__ rows,
                               const int* __restrict__ cols,
                               const float* __restrict__ vals) {
    int i = blockIdx.x * blockDim.x + threadIdx.x;
    if (i < EE) {
        int r = rows[i];
        int p = atomicAdd(&g_cursor[r], 1);
        g_cedge[p] = make_int2(cols[i], __float_as_int(vals[i]));
    }
}

// ---------------- W0 transpose -> fp16 -------------------------------------------
__global__ void w0_half_kernel(const float* __restrict__ W0) {
    int i = blockIdx.x * blockDim.x + threadIdx.x;   // over K1*HD
    if (i < K1 * HD) {
        int k = i / HD, n = i % HD;
        g_W0t_h[n * K1 + k] = __float2half(W0[i]);
    }
}

// ---------------- GEMM1 via mma.sync fp16 single product, fp16 out ---------------
#define G1_KC   32
#define G1_NC   (K1 / G1_KC)
#define G1_STR  40
#define G1_BUF  20480                  // A 10240 | B 10240
#define G1_SMEM (2 * G1_BUF)

__global__ void __launch_bounds__(256, 2) gemm1_mma_kernel(const float* __restrict__ A) {
    extern __shared__ __align__(16) char smem[];
    uint32_t sb = smem_u32(smem);

    int tid  = threadIdx.x;
    int lane = tid & 31;
    int wid  = tid >> 5;
    int wm   = wid >> 2;
    int wn   = wid & 3;
    int row0 = blockIdx.x * 128;
    int col0 = blockIdx.y * 128;

    int a_row = tid >> 3;              // 0..31 (+p*32)
    int a_kc  = (tid & 7) * 4;         // float4 col
    int b_row = tid >> 1;              // 0..127
    int b_kc  = (tid & 1) * 16;        // halves; two uint4 at +0,+8

    float4 aS[4];
    uint4  bS[2];

    uint32_t a_ld_off = (uint32_t)((wm * 64 + (lane & 15)) * G1_STR + ((lane >> 4) << 3)) * 2;
    uint32_t b_ld_off = (uint32_t)((wn * 32 + (lane & 7) + ((lane >> 4) << 3)) * G1_STR
                                   + (((lane >> 3) & 1) << 3)) * 2;

    float acc[4][4][4];
    #pragma unroll
    for (int i = 0; i < 4; i++)
        #pragma unroll
        for (int j = 0; j < 4; j++)
            #pragma unroll
            for (int t = 0; t < 4; t++) acc[i][j][t] = 0.f;

    auto load_stage = [&](int kt) {
        #pragma unroll
        for (int p = 0; p < 4; p++) {
            int r = row0 + a_row + p * 32;
            aS[p] = (r < NN)
                ? *reinterpret_cast<const float4*>(A + (size_t)r * K1 + kt + a_kc)
                : make_float4(0.f, 0.f, 0.f, 0.f);
        }
        int n = col0 + b_row;
        #pragma unroll
        for (int p = 0; p < 2; p++)
            bS[p] = *reinterpret_cast<const uint4*>(g_W0t_h + (size_t)n * K1 + kt + b_kc + p * 8);
    };

    auto store_stage = [&](int buf) {
        char* base = smem + buf * G1_BUF;
        #pragma unroll
        for (int p = 0; p < 4; p++) {
            float4 v = aS[p];
            __half2 h01 = __floats2half2_rn(v.x, v.y);
            __half2 h23 = __floats2half2_rn(v.z, v.w);
            uint32_t off = (uint32_t)((a_row + p * 32) * G1_STR + a_kc) * 2;
            *reinterpret_cast<uint2*>(base + off) =
                make_uint2(*(uint32_t*)&h01, *(uint32_t*)&h23);
        }
        #pragma unroll
        for (int p = 0; p < 2; p++) {
            uint32_t off = (uint32_t)(b_row * G1_STR + b_kc + p * 8) * 2;
            *reinterpret_cast<uint4*>(base + 10240 + off) = bS[p];
        }
    };

    auto compute = [&](int buf) {
        uint32_t ab = sb + buf * G1_BUF;
        #pragma unroll
        for (int ks = 0; ks < 2; ks++) {
            uint32_t kso = (uint32_t)(ks * 16) * 2;
            uint32_t ah[4][4], bh[4][2];
            #pragma unroll
            for (int i = 0; i < 4; i++) {
                uint32_t ao = ab + a_ld_off + kso + (uint32_t)(i * 16 * G1_STR) * 2;
                ldmx4(ah[i], ao);
            }
            #pragma unroll
            for (int j2 = 0; j2 < 2; j2++) {
                uint32_t bo = ab + 10240 + b_ld_off + kso + (uint32_t)(j2 * 16 * G1_STR) * 2;
                uint32_t t[4];
                ldmx4(t, bo);
                bh[j2 * 2][0] = t[0]; bh[j2 * 2][1] = t[1];
                bh[j2 * 2 + 1][0] = t[2]; bh[j2 * 2 + 1][1] = t[3];
            }
            #pragma unroll
            for (int i = 0; i < 4; i++)
                #pragma unroll
                for (int j = 0; j < 4; j++)
                    mma16816h(acc[i][j], ah[i], bh[j][0], bh[j][1]);
        }
    };

    load_stage(0);
    store_stage(0);
    __syncthreads();

    for (int c = 0; c < G1_NC; c++) {
        if (c + 1 < G1_NC) load_stage((c + 1) * G1_KC);
        compute(c & 1);
        if (c + 1 < G1_NC) store_stage((c + 1) & 1);
        __syncthreads();
    }

    // epilogue -> fp16
    #pragma unroll
    for (int i = 0; i < 4; i++) {
        int r0 = row0 + wm * 64 + i * 16 + (lane >> 2);
        #pragma unroll
        for (int j = 0; j < 4; j++) {
            int cidx = col0 + wn * 32 + j * 8 + (lane & 3) * 2;
            if (r0 < NN)
                *reinterpret_cast<__half2*>(g_XW0h + (size_t)r0 * HD + cidx) =
                    __floats2half2_rn(acc[i][j][0], acc[i][j][1]);
            if (r0 + 8 < NN)
                *reinterpret_cast<__half2*>(g_XW0h + (size_t)(r0 + 8) * HD + cidx) =
                    __floats2half2_rn(acc[i][j][2], acc[i][j][3]);
        }
    }
}

// ---------------- SpMM1: H1 = relu(A @ XW0h) -> fp32, warp per row ----------------
__device__ __forceinline__ void fmah8(float* acc, float v, const uint4& q) {
    const __half2* h = reinterpret_cast<const __half2*>(&q);
    #pragma unroll
    for (int t = 0; t < 4; t++) {
        float2 f = __half22float2(h[t]);
        acc[2 * t]     = fmaf(v, f.x, acc[2 * t]);
        acc[2 * t + 1] = fmaf(v, f.y, acc[2 * t + 1]);
    }
}

__global__ void __launch_bounds__(256) spmm1_relu_kernel() {
    int w    = (blockIdx.x * blockDim.x + threadIdx.x) >> 5;
    int lane = threadIdx.x & 31;
    if (w >= NN) return;

    int s = g_rowptr[w], e = g_rowptr[w + 1];
    const uint4* Yh = reinterpret_cast<const uint4*>(g_XW0h);  // 32 uint4 per row

    float acc[8];
    #pragma unroll
    for (int t = 0; t < 8; t++) acc[t] = 0.f;

    int i = s;
    for (; i + 4 <= e; i += 4) {
        int2 e0 = g_cedge[i],     e1 = g_cedge[i + 1];
        int2 e2 = g_cedge[i + 2], e3 = g_cedge[i + 3];
        uint4 q0 = Yh[(size_t)e0.x * 32 + lane];
        uint4 q1 = Yh[(size_t)e1.x * 32 + lane];
        uint4 q2 = Yh[(size_t)e2.x * 32 + lane];
        uint4 q3 = Yh[(size_t)e3.x * 32 + lane];
        fmah8(acc, __int_as_float(e0.y), q0);
        fmah8(acc, __int_as_float(e1.y), q1);
        fmah8(acc, __int_as_float(e2.y), q2);
        fmah8(acc, __int_as_float(e3.y), q3);
    }
    for (; i < e; i++) {
        int2 ed = g_cedge[i];
        uint4 q = Yh[(size_t)ed.x * 32 + lane];
        fmah8(acc, __int_as_float(ed.y), q);
    }

    float* dst = g_H1 + (size_t)w * HD + lane * 8;
    *reinterpret_cast<float4*>(dst) =
        make_float4(fmaxf(acc[0], 0.f), fmaxf(acc[1], 0.f),
                    fmaxf(acc[2], 0.f), fmaxf(acc[3], 0.f));
    *reinterpret_cast<float4*>(dst + 4) =
        make_float4(fmaxf(acc[4], 0.f), fmaxf(acc[5], 0.f),
                    fmaxf(acc[6], 0.f), fmaxf(acc[7], 0.f));
}

// ---------------- GEMM2: H1W1 = H1 @ W1 (FFMA2, known good) ------------------------
__global__ void __launch_bounds__(256) gemm2_kernel(const float* __restrict__ B) {
    const int K = HD, Nc = FD;
    __shared__ float As[16][68];
    __shared__ float Bs[16][64];

    int tid  = threadIdx.x;
    int row0 = blockIdx.x * 64;

    int ar = tid >> 2;
    int ak = (tid & 3) * 4;
    int bk = tid >> 4;
    int bc = (tid & 15) * 4;

    int ty = tid >> 4, tx = tid & 15;

    unsigned long long acc2[4][2];
    #pragma unroll
    for (int i = 0; i < 4; i++) { acc2[i][0] = 0ull; acc2[i][1] = 0ull; }

    for (int kt = 0; kt < K; kt += 16) {
        float4 av = make_float4(0.f, 0.f, 0.f, 0.f);
        int arow = row0 + ar;
        if (arow < NN)
            av = *reinterpret_cast<const float4*>(g_H1 + (size_t)arow * K + kt + ak);
        As[ak + 0][ar] = av.x; As[ak + 1][ar] = av.y;
        As[ak + 2][ar] = av.z; As[ak + 3][ar] = av.w;

        float4 bv = *reinterpret_cast<const float4*>(B + (size_t)(kt + bk) * Nc + bc);
        *reinterpret_cast<float4*>(&Bs[bk][bc]) = bv;
        __syncthreads();

        #pragma unroll
        for (int k = 0; k < 16; k++) {
            float4 a = *reinterpret_cast<float4*>(&As[k][ty * 4]);
            unsigned long long b2[2];
            *reinterpret_cast<float4*>(&b2[0]) = *reinterpret_cast<float4*>(&Bs[k][tx * 4]);
            float aa[4] = {a.x, a.y, a.z, a.w};
            #pragma unroll
            for (int i = 0; i < 4; i++) {
                unsigned long long a2 = pk2(aa[i], aa[i]);
                acc2[i][0] = ffma2(a2, b2[0], acc2[i][0]);
                acc2[i][1] = ffma2(a2, b2[1], acc2[i][1]);
            }
        }
        __syncthreads();
    }

    #pragma unroll
    for (int i = 0; i < 4; i++) {
        int r = row0 + ty * 4 + i;
        if (r < NN) {
            float2 p0 = upk2(acc2[i][0]), p1 = upk2(acc2[i][1]);
            *reinterpret_cast<float4*>(g_H1W1 + (size_t)r * Nc + tx * 4) =
                make_float4(p0.x, p0.y, p1.x, p1.y);
        }
    }
}

// ---------------- SpMM2 + softmax -------------------------------------------------
__global__ void __launch_bounds__(256) spmm2_softmax_kernel(float* __restrict__ out) {
    int w    = (blockIdx.x * blockDim.x + threadIdx.x) >> 5;
    int lane = threadIdx.x & 31;
    if (w >= NN) return;

    int s = g_rowptr[w], e = g_rowptr[w + 1];
    const float2* Y2 = reinterpret_cast<const float2*>(g_H1W1);

    float ax = 0.f, ay = 0.f;
    int i = s;
    for (; i + 4 <= e; i += 4) {
        int2 e0 = g_cedge[i],     e1 = g_cedge[i + 1];
        int2 e2 = g_cedge[i + 2], e3 = g_cedge[i + 3];
        float2 y0 = Y2[(size_t)e0.x * 32 + lane];
        float2 y1 = Y2[(size_t)e1.x * 32 + lane];
        float2 y2 = Y2[(size_t)e2.x * 32 + lane];
        float2 y3 = Y2[(size_t)e3.x * 32 + lane];
        float v0 = __int_as_float(e0.y), v1 = __int_as_float(e1.y);
        float v2 = __int_as_float(e2.y), v3 = __int_as_float(e3.y);
        ax = fmaf(v0, y0.x, ax); ay = fmaf(v0, y0.y, ay);
        ax = fmaf(v1, y1.x, ax); ay = fmaf(v1, y1.y, ay);
        ax = fmaf(v2, y2.x, ax); ay = fmaf(v2, y2.y, ay);
        ax = fmaf(v3, y3.x, ax); ay = fmaf(v3, y3.y, ay);
    }
    for (; i < e; i++) {
        int2 ed = g_cedge[i];
        float v = __int_as_float(ed.y);
        float2 y = Y2[(size_t)ed.x * 32 + lane];
        ax = fmaf(v, y.x, ax); ay = fmaf(v, y.y, ay);
    }

    float m = fmaxf(ax, ay);
    #pragma unroll
    for (int o = 16; o; o >>= 1) m = fmaxf(m, __shfl_xor_sync(0xffffffffu, m, o));
    float e0 = expf(ax - m), e1 = expf(ay - m);
    float sum = e0 + e1;
    #pragma unroll
    for (int o = 16; o; o >>= 1) sum += __shfl_xor_sync(0xffffffffu, sum, o);
    float inv = 1.f / sum;

    reinterpret_cast<float2*>(out)[(size_t)w * 32 + lane] = make_float2(e0 * inv, e1 * inv);
}

// ---------------- launcher ----------------------------------------------------------
extern "C" void kernel_launch(void* const* d_in, const int* in_sizes, int n_in,
                              void* d_out, int out_size) {
    const float* X  = (const float*)d_in[0];
    const int*   er = (const int*)d_in[1];
    const int*   ec = (const int*)d_in[2];
    const float* ev = (const float*)d_in[3];
    const float* W0 = (const float*)d_in[4];
    const float* W1 = (const float*)d_in[5];
    float* out = (float*)d_out;

    static bool attr_done = false;
    if (!attr_done) {
        cudaFuncSetAttribute(gemm1_mma_kernel,
                             cudaFuncAttributeMaxDynamicSharedMemorySize, G1_SMEM);
        attr_done = true;
    }

    // CSR build
    zero_cnt_kernel<<<(NN + 255) / 256, 256>>>();
    hist_kernel<<<(EE / 4 + 255) / 256, 256>>>((const int4*)er);
    scan_kernel<<<1, 1024>>>();
    scatter_kernel<<<(EE + 255) / 256, 256>>>(er, ec, ev);

    // W0 prep + Layer 1
    w0_half_kernel<<<(K1 * HD + 255) / 256, 256>>>(W0);
    {
        dim3 grid((NN + 127) / 128, HD / 128);
        gemm1_mma_kernel<<<grid, 256, G1_SMEM>>>(X);
    }
    spmm1_relu_kernel<<<(NN * 32 + 255) / 256, 256>>>();

    // Layer 2
    gemm2_kernel<<<(NN + 63) / 64, 256>>>(W1);
    spmm2_softmax_kernel<<<(NN * 32 + 255) / 256, 256>>>(out);
}

// round 9
// speedup vs baseline: 3.1857x; 1.0912x over previous
#include <cuda_runtime.h>
#include <cuda_bf16.h>
#include <cuda_fp16.h>
#include <cstdint>

#define NN 100000
#define EE 3200000
#define K1 512
#define HD 256
#define FD 64

// ---------------- scratch -----------------------------------------------------
__device__ __align__(16) __half g_XW0h[NN * HD];    // X @ W0 fp16 (51 MB)
__device__ __align__(16) float g_H1[NN * HD];       // relu(A @ XW0) fp32
__device__ __align__(16) float g_H1W1[NN * FD];     // logits precursor fp32
__device__ int   g_rowptr[NN + 1];
__device__ int   g_cursor[NN];
__device__ int   g_cnt[NN];
__device__ __align__(16) int2 g_cedge[EE];          // (col, valbits) fused
__device__ __align__(16) __half g_W0t_h[HD * K1];   // W0^T fp16 [256][512]
__device__ __align__(16) __nv_bfloat16 g_W1t_hi[FD * HD];  // W1^T split [64][256]
__device__ __align__(16) __nv_bfloat16 g_W1t_lo[FD * HD];

// ---------------- helpers ------------------------------------------------------
__device__ __forceinline__ uint32_t smem_u32(const void* p) {
    uint32_t a;
    asm("{ .reg .u64 t; cvta.to.shared.u64 t, %1; cvt.u32.u64 %0, t; }" : "=r"(a) : "l"(p));
    return a;
}
__device__ __forceinline__ void ldmx4(uint32_t* d, uint32_t addr) {
    asm volatile("ldmatrix.sync.aligned.m8n8.x4.shared.b16 {%0,%1,%2,%3}, [%4];"
                 : "=r"(d[0]), "=r"(d[1]), "=r"(d[2]), "=r"(d[3]) : "r"(addr));
}
__device__ __forceinline__ void mma16816h(float* c, const uint32_t* a, uint32_t b0, uint32_t b1) {
    asm volatile("mma.sync.aligned.m16n8k16.row.col.f32.f16.f16.f32 "
                 "{%0,%1,%2,%3}, {%4,%5,%6,%7}, {%8,%9}, {%0,%1,%2,%3};"
                 : "+f"(c[0]), "+f"(c[1]), "+f"(c[2]), "+f"(c[3])
                 : "r"(a[0]), "r"(a[1]), "r"(a[2]), "r"(a[3]), "r"(b0), "r"(b1));
}
__device__ __forceinline__ void mma16816b(float* c, const uint32_t* a, uint32_t b0, uint32_t b1) {
    asm volatile("mma.sync.aligned.m16n8k16.row.col.f32.bf16.bf16.f32 "
                 "{%0,%1,%2,%3}, {%4,%5,%6,%7}, {%8,%9}, {%0,%1,%2,%3};"
                 : "+f"(c[0]), "+f"(c[1]), "+f"(c[2]), "+f"(c[3])
                 : "r"(a[0]), "r"(a[1]), "r"(a[2]), "r"(a[3]), "r"(b0), "r"(b1));
}

// ---------------- CSR build -----------------------------------------------------
__global__ void zero_cnt_kernel() {
    int i = blockIdx.x * blockDim.x + threadIdx.x;
    if (i < NN) g_cnt[i] = 0;
}
__global__ void hist_kernel(const int4* __restrict__ rows4) {
    int i = blockIdx.x * blockDim.x + threadIdx.x;
    if (i < EE / 4) {
        int4 r = rows4[i];
        atomicAdd(&g_cnt[r.x], 1);
        atomicAdd(&g_cnt[r.y], 1);
        atomicAdd(&g_cnt[r.z], 1);
        atomicAdd(&g_cnt[r.w], 1);
    }
}
__global__ void __launch_bounds__(1024) scan_kernel() {
    __shared__ int wsum[32];
    int tid = threadIdx.x;
    const int PER = 98;
    int base = tid * PER;
    int s = 0;
    for (int j = 0; j < PER; j++) {
        int i = base + j;
        if (i < NN) s += g_cnt[i];
    }
    int lane = tid & 31, wid = tid >> 5;
    int x = s;
    #pragma unroll
    for (int o = 1; o < 32; o <<= 1) {
        int t = __shfl_up_sync(0xffffffffu, x, o);
        if (lane >= o) x += t;
    }
    if (lane == 31) wsum[wid] = x;
    __syncthreads();
    if (wid == 0) {
        int w = wsum[lane];
        #pragma unroll
        for (int o = 1; o < 32; o <<= 1) {
            int t = __shfl_up_sync(0xffffffffu, w, o);
            if (lane >= o) w += t;
        }
        wsum[lane] = w;
    }
    __syncthreads();
    int excl = x - s + (wid > 0 ? wsum[wid - 1] : 0);
    int run = excl;
    for (int j = 0; j < PER; j++) {
        int i = base + j;
        if (i < NN) {
            g_rowptr[i] = run;
            g_cursor[i] = run;
            run += g_cnt[i];
        }
    }
    if (tid == 1023) g_rowptr[NN] = run;
}
__global__ void scatter_kernel(const int* __restrict__ rows,
                               const int* __restrict__ cols,
                               const float* __restrict__ vals) {
    int i = blockIdx.x * blockDim.x + threadIdx.x;
    if (i < EE) {
        int r = rows[i];
        int p = atomicAdd(&g_cursor[r], 1);
        g_cedge[p] = make_int2(cols[i], __float_as_int(vals[i]));
    }
}

// ---------------- weight prep -----------------------------------------------------
__global__ void w0_half_kernel(const float* __restrict__ W0) {
    int i = blockIdx.x * blockDim.x + threadIdx.x;
    if (i < K1 * HD) {
        int k = i / HD, n = i % HD;
        g_W0t_h[n * K1 + k] = __float2half(W0[i]);
    }
}
__global__ void w1_split_kernel(const float* __restrict__ W1) {
    int i = blockIdx.x * blockDim.x + threadIdx.x;
    if (i < HD * FD) {
        int k = i / FD, n = i % FD;
        float v = W1[i];
        __nv_bfloat16 h = __float2bfloat16(v);
        g_W1t_hi[n * HD + k] = h;
        g_W1t_lo[n * HD + k] = __float2bfloat16(v - __bfloat162float(h));
    }
}

// ---------------- GEMM1 via mma.sync fp16, fp16 out ------------------------------
#define G1_KC   32
#define G1_NC   (K1 / G1_KC)
#define G1_STR  40
#define G1_BUF  20480                  // A 10240 | B 10240
#define G1_SMEM (2 * G1_BUF)

__global__ void __launch_bounds__(256, 2) gemm1_mma_kernel(const float* __restrict__ A) {
    extern __shared__ __align__(16) char smem[];
    uint32_t sb = smem_u32(smem);

    int tid  = threadIdx.x;
    int lane = tid & 31;
    int wid  = tid >> 5;
    int wm   = wid >> 2;
    int wn   = wid & 3;
    int row0 = blockIdx.x * 128;
    int col0 = blockIdx.y * 128;

    int a_row = tid >> 3;
    int a_kc  = (tid & 7) * 4;
    int b_row = tid >> 1;
    int b_kc  = (tid & 1) * 16;

    float4 aS[4];
    uint4  bS[2];

    uint32_t a_ld_off = (uint32_t)((wm * 64 + (lane & 15)) * G1_STR + ((lane >> 4) << 3)) * 2;
    uint32_t b_ld_off = (uint32_t)((wn * 32 + (lane & 7) + ((lane >> 4) << 3)) * G1_STR
                                   + (((lane >> 3) & 1) << 3)) * 2;

    float acc[4][4][4];
    #pragma unroll
    for (int i = 0; i < 4; i++)
        #pragma unroll
        for (int j = 0; j < 4; j++)
            #pragma unroll
            for (int t = 0; t < 4; t++) acc[i][j][t] = 0.f;

    auto load_stage = [&](int kt) {
        #pragma unroll
        for (int p = 0; p < 4; p++) {
            int r = row0 + a_row + p * 32;
            aS[p] = (r < NN)
                ? *reinterpret_cast<const float4*>(A + (size_t)r * K1 + kt + a_kc)
                : make_float4(0.f, 0.f, 0.f, 0.f);
        }
        int n = col0 + b_row;
        #pragma unroll
        for (int p = 0; p < 2; p++)
            bS[p] = *reinterpret_cast<const uint4*>(g_W0t_h + (size_t)n * K1 + kt + b_kc + p * 8);
    };

    auto store_stage = [&](int buf) {
        char* base = smem + buf * G1_BUF;
        #pragma unroll
        for (int p = 0; p < 4; p++) {
            float4 v = aS[p];
            __half2 h01 = __floats2half2_rn(v.x, v.y);
            __half2 h23 = __floats2half2_rn(v.z, v.w);
            uint32_t off = (uint32_t)((a_row + p * 32) * G1_STR + a_kc) * 2;
            *reinterpret_cast<uint2*>(base + off) =
                make_uint2(*(uint32_t*)&h01, *(uint32_t*)&h23);
        }
        #pragma unroll
        for (int p = 0; p < 2; p++) {
            uint32_t off = (uint32_t)(b_row * G1_STR + b_kc + p * 8) * 2;
            *reinterpret_cast<uint4*>(base + 10240 + off) = bS[p];
        }
    };

    auto compute = [&](int buf) {
        uint32_t ab = sb + buf * G1_BUF;
        #pragma unroll
        for (int ks = 0; ks < 2; ks++) {
            uint32_t kso = (uint32_t)(ks * 16) * 2;
            uint32_t ah[4][4], bh[4][2];
            #pragma unroll
            for (int i = 0; i < 4; i++) {
                uint32_t ao = ab + a_ld_off + kso + (uint32_t)(i * 16 * G1_STR) * 2;
                ldmx4(ah[i], ao);
            }
            #pragma unroll
            for (int j2 = 0; j2 < 2; j2++) {
                uint32_t bo = ab + 10240 + b_ld_off + kso + (uint32_t)(j2 * 16 * G1_STR) * 2;
                uint32_t t[4];
                ldmx4(t, bo);
                bh[j2 * 2][0] = t[0]; bh[j2 * 2][1] = t[1];
                bh[j2 * 2 + 1][0] = t[2]; bh[j2 * 2 + 1][1] = t[3];
            }
            #pragma unroll
            for (int i = 0; i < 4; i++)
                #pragma unroll
                for (int j = 0; j < 4; j++)
                    mma16816h(acc[i][j], ah[i], bh[j][0], bh[j][1]);
        }
    };

    load_stage(0);
    store_stage(0);
    __syncthreads();

    for (int c = 0; c < G1_NC; c++) {
        if (c + 1 < G1_NC) load_stage((c + 1) * G1_KC);
        compute(c & 1);
        if (c + 1 < G1_NC) store_stage((c + 1) & 1);
        __syncthreads();
    }

    #pragma unroll
    for (int i = 0; i < 4; i++) {
        int r0 = row0 + wm * 64 + i * 16 + (lane >> 2);
        #pragma unroll
        for (int j = 0; j < 4; j++) {
            int cidx = col0 + wn * 32 + j * 8 + (lane & 3) * 2;
            if (r0 < NN)
                *reinterpret_cast<__half2*>(g_XW0h + (size_t)r0 * HD + cidx) =
                    __floats2half2_rn(acc[i][j][0], acc[i][j][1]);
            if (r0 + 8 < NN)
                *reinterpret_cast<__half2*>(g_XW0h + (size_t)(r0 + 8) * HD + cidx) =
                    __floats2half2_rn(acc[i][j][2], acc[i][j][3]);
        }
    }
}

// ---------------- SpMM1: H1 = relu(A @ XW0h) -> fp32, warp per row ----------------
__device__ __forceinline__ void fmah8(float* acc, float v, const uint4& q) {
    const __half2* h = reinterpret_cast<const __half2*>(&q);
    #pragma unroll
    for (int t = 0; t < 4; t++) {
        float2 f = __half22float2(h[t]);
        acc[2 * t]     = fmaf(v, f.x, acc[2 * t]);
        acc[2 * t + 1] = fmaf(v, f.y, acc[2 * t + 1]);
    }
}

__global__ void __launch_bounds__(256) spmm1_relu_kernel() {
    int w    = (blockIdx.x * blockDim.x + threadIdx.x) >> 5;
    int lane = threadIdx.x & 31;
    if (w >= NN) return;

    int s = g_rowptr[w], e = g_rowptr[w + 1];
    const uint4* Yh = reinterpret_cast<const uint4*>(g_XW0h);

    float acc[8];
    #pragma unroll
    for (int t = 0; t < 8; t++) acc[t] = 0.f;

    int i = s;
    for (; i + 8 <= e; i += 8) {
        int2 ed[8];
        uint4 q[8];
        #pragma unroll
        for (int u = 0; u < 8; u++) ed[u] = g_cedge[i + u];
        #pragma unroll
        for (int u = 0; u < 8; u++) q[u] = Yh[(size_t)ed[u].x * 32 + lane];
        #pragma unroll
        for (int u = 0; u < 8; u++) fmah8(acc, __int_as_float(ed[u].y), q[u]);
    }
    for (; i + 4 <= e; i += 4) {
        int2 e0 = g_cedge[i],     e1 = g_cedge[i + 1];
        int2 e2 = g_cedge[i + 2], e3 = g_cedge[i + 3];
        uint4 q0 = Yh[(size_t)e0.x * 32 + lane];
        uint4 q1 = Yh[(size_t)e1.x * 32 + lane];
        uint4 q2 = Yh[(size_t)e2.x * 32 + lane];
        uint4 q3 = Yh[(size_t)e3.x * 32 + lane];
        fmah8(acc, __int_as_float(e0.y), q0);
        fmah8(acc, __int_as_float(e1.y), q1);
        fmah8(acc, __int_as_float(e2.y), q2);
        fmah8(acc, __int_as_float(e3.y), q3);
    }
    for (; i < e; i++) {
        int2 ed = g_cedge[i];
        uint4 q = Yh[(size_t)ed.x * 32 + lane];
        fmah8(acc, __int_as_float(ed.y), q);
    }

    float* dst = g_H1 + (size_t)w * HD + lane * 8;
    *reinterpret_cast<float4*>(dst) =
        make_float4(fmaxf(acc[0], 0.f), fmaxf(acc[1], 0.f),
                    fmaxf(acc[2], 0.f), fmaxf(acc[3], 0.f));
    *reinterpret_cast<float4*>(dst + 4) =
        make_float4(fmaxf(acc[4], 0.f), fmaxf(acc[5], 0.f),
                    fmaxf(acc[6], 0.f), fmaxf(acc[7], 0.f));
}

// ---------------- GEMM2 via mma.sync split-bf16 (3 products): fp32 in/out ---------
// CTA 128(M) x 64(N), K=256 in chunks of 32, 8 warps = 4(M) x 2(N), warp tile 32x32.
// A (fp32 H1) converted to bf16 hi/lo in SMEM; B = pre-split W1^T.
#define G2_KC   32
#define G2_NC   (HD / G2_KC)          // 8
#define G2_STR  40
#define G2_AH   0                     // Ah 10240
#define G2_AL   10240                 // Al 10240
#define G2_BH   20480                 // Bh 5120
#define G2_BL   25600                 // Bl 5120
#define G2_BUF  30720
#define G2_SMEM (2 * G2_BUF)

__global__ void __launch_bounds__(256) gemm2_mma_kernel() {
    extern __shared__ __align__(16) char smem[];
    uint32_t sb = smem_u32(smem);

    int tid  = threadIdx.x;
    int lane = tid & 31;
    int wid  = tid >> 5;
    int wm   = wid >> 1;              // 0..3
    int wn   = wid & 1;               // 0..1
    int row0 = blockIdx.x * 128;

    int a_row = tid >> 3;             // 0..31 (+p*32), fp32 float4 = 4 cols
    int a_kc  = (tid & 3) * 8;        // two float4 at +0,+4  (8 cols per thread-pair group)
    int a_sel = (tid >> 2) & 1;       // unused split — keep simple: use 8 threads/row
    // simpler mapping: 8 threads per row, each thread loads 4 fp32 (float4)
    int ar8   = tid >> 3;             // 0..31
    int ac8   = (tid & 7) * 4;        // 0..28 step 4
    int b_row = tid >> 2;             // 0..63
    int b_kc  = (tid & 3) * 8;        // 8 bf16 per uint4

    float4 aS[4];
    uint4  bhS, blS;

    uint32_t a_ld_off = (uint32_t)((wm * 32 + (lane & 15)) * G2_STR + ((lane >> 4) << 3)) * 2;
    uint32_t b_ld_off = (uint32_t)((wn * 32 + (lane & 7) + ((lane >> 4) << 3)) * G2_STR
                                   + (((lane >> 3) & 1) << 3)) * 2;

    float acc[2][4][4];
    #pragma unroll
    for (int i = 0; i < 2; i++)
        #pragma unroll
        for (int j = 0; j < 4; j++)
            #pragma unroll
            for (int t = 0; t < 4; t++) acc[i][j][t] = 0.f;

    auto load_stage = [&](int kt) {
        #pragma unroll
        for (int p = 0; p < 4; p++) {
            int r = row0 + ar8 + p * 32;
            aS[p] = (r < NN)
                ? *reinterpret_cast<const float4*>(g_H1 + (size_t)r * HD + kt + ac8)
                : make_float4(0.f, 0.f, 0.f, 0.f);
        }
        bhS = *reinterpret_cast<const uint4*>(g_W1t_hi + (size_t)b_row * HD + kt + b_kc);
        blS = *reinterpret_cast<const uint4*>(g_W1t_lo + (size_t)b_row * HD + kt + b_kc);
    };

    auto store_stage = [&](int buf) {
        char* base = smem + buf * G2_BUF;
        #pragma unroll
        for (int p = 0; p < 4; p++) {
            float4 v = aS[p];
            __nv_bfloat162 h01 = __floats2bfloat162_rn(v.x, v.y);
            __nv_bfloat162 h23 = __floats2bfloat162_rn(v.z, v.w);
            float2 f01 = __bfloat1622float2(h01);
            float2 f23 = __bfloat1622float2(h23);
            __nv_bfloat162 l01 = __floats2bfloat162_rn(v.x - f01.x, v.y - f01.y);
            __nv_bfloat162 l23 = __floats2bfloat162_rn(v.z - f23.x, v.w - f23.y);
            uint32_t off = (uint32_t)((ar8 + p * 32) * G2_STR + ac8) * 2;
            *reinterpret_cast<uint2*>(base + G2_AH + off) =
                make_uint2(*(uint32_t*)&h01, *(uint32_t*)&h23);
            *reinterpret_cast<uint2*>(base + G2_AL + off) =
                make_uint2(*(uint32_t*)&l01, *(uint32_t*)&l23);
        }
        uint32_t boff = (uint32_t)(b_row * G2_STR + b_kc) * 2;
        *reinterpret_cast<uint4*>(base + G2_BH + boff) = bhS;
        *reinterpret_cast<uint4*>(base + G2_BL + boff) = blS;
    };

    auto compute = [&](int buf) {
        uint32_t ab = sb + buf * G2_BUF;
        #pragma unroll
        for (int ks = 0; ks < 2; ks++) {
            uint32_t kso = (uint32_t)(ks * 16) * 2;
            uint32_t ah[2][4], al[2][4], bh[4][2], bl[4][2];
            #pragma unroll
            for (int i = 0; i < 2; i++) {
                uint32_t ao = ab + a_ld_off + kso + (uint32_t)(i * 16 * G2_STR) * 2;
                ldmx4(ah[i], ao + G2_AH);
                ldmx4(al[i], ao + G2_AL);
            }
            #pragma unroll
            for (int j2 = 0; j2 < 2; j2++) {
                uint32_t bo = ab + b_ld_off + kso + (uint32_t)(j2 * 16 * G2_STR) * 2;
                uint32_t t[4];
                ldmx4(t, bo + G2_BH);
                bh[j2 * 2][0] = t[0]; bh[j2 * 2][1] = t[1];
                bh[j2 * 2 + 1][0] = t[2]; bh[j2 * 2 + 1][1] = t[3];
                ldmx4(t, bo + G2_BL);
                bl[j2 * 2][0] = t[0]; bl[j2 * 2][1] = t[1];
                bl[j2 * 2 + 1][0] = t[2]; bl[j2 * 2 + 1][1] = t[3];
            }
            #pragma unroll
            for (int i = 0; i < 2; i++)
                #pragma unroll
                for (int j = 0; j < 4; j++) {
                    mma16816b(acc[i][j], ah[i], bh[j][0], bh[j][1]);
                    mma16816b(acc[i][j], ah[i], bl[j][0], bl[j][1]);
                    mma16816b(acc[i][j], al[i], bh[j][0], bh[j][1]);
                }
        }
    };

    load_stage(0);
    store_stage(0);
    __syncthreads();

    for (int c = 0; c < G2_NC; c++) {
        if (c + 1 < G2_NC) load_stage((c + 1) * G2_KC);
        compute(c & 1);
        if (c + 1 < G2_NC) store_stage((c + 1) & 1);
        __syncthreads();
    }

    #pragma unroll
    for (int i = 0; i < 2; i++) {
        int r0 = row0 + wm * 32 + i * 16 + (lane >> 2);
        #pragma unroll
        for (int j = 0; j < 4; j++) {
            int cidx = wn * 32 + j * 8 + (lane & 3) * 2;
            if (r0 < NN)
                *reinterpret_cast<float2*>(g_H1W1 + (size_t)r0 * FD + cidx) =
                    make_float2(acc[i][j][0], acc[i][j][1]);
            if (r0 + 8 < NN)
                *reinterpret_cast<float2*>(g_H1W1 + (size_t)(r0 + 8) * FD + cidx) =
                    make_float2(acc[i][j][2], acc[i][j][3]);
        }
    }
}

// ---------------- SpMM2 + softmax (fp32 gather) -----------------------------------
__global__ void __launch_bounds__(256) spmm2_softmax_kernel(float* __restrict__ out) {
    int w    = (blockIdx.x * blockDim.x + threadIdx.x) >> 5;
    int lane = threadIdx.x & 31;
    if (w >= NN) return;

    int s = g_rowptr[w], e = g_rowptr[w + 1];
    const float2* Y2 = reinterpret_cast<const float2*>(g_H1W1);

    float ax = 0.f, ay = 0.f;
    int i = s;
    for (; i + 4 <= e; i += 4) {
        int2 e0 = g_cedge[i],     e1 = g_cedge[i + 1];
        int2 e2 = g_cedge[i + 2], e3 = g_cedge[i + 3];
        float2 y0 = Y2[(size_t)e0.x * 32 + lane];
        float2 y1 = Y2[(size_t)e1.x * 32 + lane];
        float2 y2 = Y2[(size_t)e2.x * 32 + lane];
        float2 y3 = Y2[(size_t)e3.x * 32 + lane];
        float v0 = __int_as_float(e0.y), v1 = __int_as_float(e1.y);
        float v2 = __int_as_float(e2.y), v3 = __int_as_float(e3.y);
        ax = fmaf(v0, y0.x, ax); ay = fmaf(v0, y0.y, ay);
        ax = fmaf(v1, y1.x, ax); ay = fmaf(v1, y1.y, ay);
        ax = fmaf(v2, y2.x, ax); ay = fmaf(v2, y2.y, ay);
        ax = fmaf(v3, y3.x, ax); ay = fmaf(v3, y3.y, ay);
    }
    for (; i < e; i++) {
        int2 ed = g_cedge[i];
        float v = __int_as_float(ed.y);
        float2 y = Y2[(size_t)ed.x * 32 + lane];
        ax = fmaf(v, y.x, ax); ay = fmaf(v, y.y, ay);
    }

    float m = fmaxf(ax, ay);
    #pragma unroll
    for (int o = 16; o; o >>= 1) m = fmaxf(m, __shfl_xor_sync(0xffffffffu, m, o));
    float e0 = expf(ax - m), e1 = expf(ay - m);
    float sum = e0 + e1;
    #pragma unroll
    for (int o = 16; o; o >>= 1) sum += __shfl_xor_sync(0xffffffffu, sum, o);
    float inv = 1.f / sum;

    reinterpret_cast<float2*>(out)[(size_t)w * 32 + lane] = make_float2(e0 * inv, e1 * inv);
}

// ---------------- launcher ----------------------------------------------------------
extern "C" void kernel_launch(void* const* d_in, const int* in_sizes, int n_in,
                              void* d_out, int out_size) {
    const float* X  = (const float*)d_in[0];
    const int*   er = (const int*)d_in[1];
    const int*   ec = (const int*)d_in[2];
    const float* ev = (const float*)d_in[3];
    const float* W0 = (const float*)d_in[4];
    const float* W1 = (const float*)d_in[5];
    float* out = (float*)d_out;

    static bool attr_done = false;
    if (!attr_done) {
        cudaFuncSetAttribute(gemm1_mma_kernel,
                             cudaFuncAttributeMaxDynamicSharedMemorySize, G1_SMEM);
        cudaFuncSetAttribute(gemm2_mma_kernel,
                             cudaFuncAttributeMaxDynamicSharedMemorySize, G2_SMEM);
        attr_done = true;
    }

    // CSR build
    zero_cnt_kernel<<<(NN + 255) / 256, 256>>>();
    hist_kernel<<<(EE / 4 + 255) / 256, 256>>>((const int4*)er);
    scan_kernel<<<1, 1024>>>();
    scatter_kernel<<<(EE + 255) / 256, 256>>>(er, ec, ev);

    // weight prep + Layer 1
    w0_half_kernel<<<(K1 * HD + 255) / 256, 256>>>(W0);
    w1_split_kernel<<<(HD * FD + 255) / 256, 256>>>(W1);
    {
        dim3 grid((NN + 127) / 128, HD / 128);
        gemm1_mma_kernel<<<grid, 256, G1_SMEM>>>(X);
    }
    spmm1_relu_kernel<<<(NN * 32 + 255) / 256, 256>>>();

    // Layer 2
    gemm2_mma_kernel<<<(NN + 127) / 128, 256, G2_SMEM>>>();
    spmm2_softmax_kernel<<<(NN * 32 + 255) / 256, 256>>>(out);
}

// round 10
// speedup vs baseline: 4.0066x; 1.2577x over previous
#include <cuda_runtime.h>
#include <cuda_bf16.h>
#include <cuda_fp16.h>
#include <cstdint>

#define NN 100000
#define EE 3200000
#define K1 512
#define HD 256
#define FD 64

// ---------------- scratch -----------------------------------------------------
__device__ __align__(16) __half g_XW0h[NN * HD];    // X @ W0 fp16 (51 MB)
__device__ __align__(16) float g_H1[NN * HD];       // relu(A @ XW0) fp32
__device__ __align__(16) float g_H1W1[NN * FD];     // logits precursor fp32
__device__ int   g_rowptr[NN + 1];
__device__ int   g_cursor[NN];
__device__ int   g_cnt[NN];
__device__ __align__(16) int2 g_cedge[EE];          // (col, valbits) fused
__device__ __align__(16) __half g_W0t_h[HD * K1];   // W0^T fp16 [256][512]
__device__ __align__(16) __nv_bfloat16 g_W1t_hi[FD * HD];  // W1^T split [64][256]
__device__ __align__(16) __nv_bfloat16 g_W1t_lo[FD * HD];

// ---------------- helpers ------------------------------------------------------
__device__ __forceinline__ uint32_t smem_u32(const void* p) {
    uint32_t a;
    asm("{ .reg .u64 t; cvta.to.shared.u64 t, %1; cvt.u32.u64 %0, t; }" : "=r"(a) : "l"(p));
    return a;
}
__device__ __forceinline__ void ldmx4(uint32_t* d, uint32_t addr) {
    asm volatile("ldmatrix.sync.aligned.m8n8.x4.shared.b16 {%0,%1,%2,%3}, [%4];"
                 : "=r"(d[0]), "=r"(d[1]), "=r"(d[2]), "=r"(d[3]) : "r"(addr));
}
__device__ __forceinline__ void mma16816h(float* c, const uint32_t* a, uint32_t b0, uint32_t b1) {
    asm volatile("mma.sync.aligned.m16n8k16.row.col.f32.f16.f16.f32 "
                 "{%0,%1,%2,%3}, {%4,%5,%6,%7}, {%8,%9}, {%0,%1,%2,%3};"
                 : "+f"(c[0]), "+f"(c[1]), "+f"(c[2]), "+f"(c[3])
                 : "r"(a[0]), "r"(a[1]), "r"(a[2]), "r"(a[3]), "r"(b0), "r"(b1));
}
__device__ __forceinline__ void mma16816b(float* c, const uint32_t* a, uint32_t b0, uint32_t b1) {
    asm volatile("mma.sync.aligned.m16n8k16.row.col.f32.bf16.bf16.f32 "
                 "{%0,%1,%2,%3}, {%4,%5,%6,%7}, {%8,%9}, {%0,%1,%2,%3};"
                 : "+f"(c[0]), "+f"(c[1]), "+f"(c[2]), "+f"(c[3])
                 : "r"(a[0]), "r"(a[1]), "r"(a[2]), "r"(a[3]), "r"(b0), "r"(b1));
}

// ---------------- CSR build -----------------------------------------------------
__global__ void zero_cnt_kernel() {
    int i = blockIdx.x * blockDim.x + threadIdx.x;
    if (i < NN) g_cnt[i] = 0;
}
__global__ void hist_kernel(const int4* __restrict__ rows4) {
    int i = blockIdx.x * blockDim.x + threadIdx.x;
    if (i < EE / 4) {
        int4 r = rows4[i];
        atomicAdd(&g_cnt[r.x], 1);
        atomicAdd(&g_cnt[r.y], 1);
        atomicAdd(&g_cnt[r.z], 1);
        atomicAdd(&g_cnt[r.w], 1);
    }
}
__global__ void __launch_bounds__(1024) scan_kernel() {
    __shared__ int wsum[32];
    int tid = threadIdx.x;
    const int PER = 98;
    int base = tid * PER;
    int s = 0;
    for (int j = 0; j < PER; j++) {
        int i = base + j;
        if (i < NN) s += g_cnt[i];
    }
    int lane = tid & 31, wid = tid >> 5;
    int x = s;
    #pragma unroll
    for (int o = 1; o < 32; o <<= 1) {
        int t = __shfl_up_sync(0xffffffffu, x, o);
        if (lane >= o) x += t;
    }
    if (lane == 31) wsum[wid] = x;
    __syncthreads();
    if (wid == 0) {
        int w = wsum[lane];
        #pragma unroll
        for (int o = 1; o < 32; o <<= 1) {
            int t = __shfl_up_sync(0xffffffffu, w, o);
            if (lane >= o) w += t;
        }
        wsum[lane] = w;
    }
    __syncthreads();
    int excl = x - s + (wid > 0 ? wsum[wid - 1] : 0);
    int run = excl;
    for (int j = 0; j < PER; j++) {
        int i = base + j;
        if (i < NN) {
            g_rowptr[i] = run;
            g_cursor[i] = run;
            run += g_cnt[i];
        }
    }
    if (tid == 1023) g_rowptr[NN] = run;
}
__global__ void scatter_kernel(const int* __restrict__ rows,
                               const int* __restrict__ cols,
                               const float* __restrict__ vals) {
    int i = blockIdx.x * blockDim.x + threadIdx.x;
    if (i < EE) {
        int r = rows[i];
        int p = atomicAdd(&g_cursor[r], 1);
        g_cedge[p] = make_int2(cols[i], __float_as_int(vals[i]));
    }
}

// ---------------- weight prep -----------------------------------------------------
__global__ void w0_half_kernel(const float* __restrict__ W0) {
    int i = blockIdx.x * blockDim.x + threadIdx.x;
    if (i < K1 * HD) {
        int k = i / HD, n = i % HD;
        g_W0t_h[n * K1 + k] = __float2half(W0[i]);
    }
}
__global__ void w1_split_kernel(const float* __restrict__ W1) {
    int i = blockIdx.x * blockDim.x + threadIdx.x;
    if (i < HD * FD) {
        int k = i / FD, n = i % FD;
        float v = W1[i];
        __nv_bfloat16 h = __float2bfloat16(v);
        g_W1t_hi[n * HD + k] = h;
        g_W1t_lo[n * HD + k] = __float2bfloat16(v - __bfloat162float(h));
    }
}

// ---------------- GEMM1 via mma.sync fp16, fp16 out ------------------------------
#define G1_KC   32
#define G1_NC   (K1 / G1_KC)
#define G1_STR  40
#define G1_BUF  20480                  // A 10240 | B 10240
#define G1_SMEM (2 * G1_BUF)

__global__ void __launch_bounds__(256, 2) gemm1_mma_kernel(const float* __restrict__ A) {
    extern __shared__ __align__(16) char smem[];
    uint32_t sb = smem_u32(smem);

    int tid  = threadIdx.x;
    int lane = tid & 31;
    int wid  = tid >> 5;
    int wm   = wid >> 2;
    int wn   = wid & 3;
    int row0 = blockIdx.x * 128;
    int col0 = blockIdx.y * 128;

    int a_row = tid >> 3;
    int a_kc  = (tid & 7) * 4;
    int b_row = tid >> 1;
    int b_kc  = (tid & 1) * 16;

    float4 aS[4];
    uint4  bS[2];

    uint32_t a_ld_off = (uint32_t)((wm * 64 + (lane & 15)) * G1_STR + ((lane >> 4) << 3)) * 2;
    uint32_t b_ld_off = (uint32_t)((wn * 32 + (lane & 7) + ((lane >> 4) << 3)) * G1_STR
                                   + (((lane >> 3) & 1) << 3)) * 2;

    float acc[4][4][4];
    #pragma unroll
    for (int i = 0; i < 4; i++)
        #pragma unroll
        for (int j = 0; j < 4; j++)
            #pragma unroll
            for (int t = 0; t < 4; t++) acc[i][j][t] = 0.f;

    auto load_stage = [&](int kt) {
        #pragma unroll
        for (int p = 0; p < 4; p++) {
            int r = row0 + a_row + p * 32;
            aS[p] = (r < NN)
                ? *reinterpret_cast<const float4*>(A + (size_t)r * K1 + kt + a_kc)
                : make_float4(0.f, 0.f, 0.f, 0.f);
        }
        int n = col0 + b_row;
        #pragma unroll
        for (int p = 0; p < 2; p++)
            bS[p] = *reinterpret_cast<const uint4*>(g_W0t_h + (size_t)n * K1 + kt + b_kc + p * 8);
    };

    auto store_stage = [&](int buf) {
        char* base = smem + buf * G1_BUF;
        #pragma unroll
        for (int p = 0; p < 4; p++) {
            float4 v = aS[p];
            __half2 h01 = __floats2half2_rn(v.x, v.y);
            __half2 h23 = __floats2half2_rn(v.z, v.w);
            uint32_t off = (uint32_t)((a_row + p * 32) * G1_STR + a_kc) * 2;
            *reinterpret_cast<uint2*>(base + off) =
                make_uint2(*(uint32_t*)&h01, *(uint32_t*)&h23);
        }
        #pragma unroll
        for (int p = 0; p < 2; p++) {
            uint32_t off = (uint32_t)(b_row * G1_STR + b_kc + p * 8) * 2;
            *reinterpret_cast<uint4*>(base + 10240 + off) = bS[p];
        }
    };

    auto compute = [&](int buf) {
        uint32_t ab = sb + buf * G1_BUF;
        #pragma unroll
        for (int ks = 0; ks < 2; ks++) {
            uint32_t kso = (uint32_t)(ks * 16) * 2;
            uint32_t ah[4][4], bh[4][2];
            #pragma unroll
            for (int i = 0; i < 4; i++) {
                uint32_t ao = ab + a_ld_off + kso + (uint32_t)(i * 16 * G1_STR) * 2;
                ldmx4(ah[i], ao);
            }
            #pragma unroll
            for (int j2 = 0; j2 < 2; j2++) {
                uint32_t bo = ab + 10240 + b_ld_off + kso + (uint32_t)(j2 * 16 * G1_STR) * 2;
                uint32_t t[4];
                ldmx4(t, bo);
                bh[j2 * 2][0] = t[0]; bh[j2 * 2][1] = t[1];
                bh[j2 * 2 + 1][0] = t[2]; bh[j2 * 2 + 1][1] = t[3];
            }
            #pragma unroll
            for (int i = 0; i < 4; i++)
                #pragma unroll
                for (int j = 0; j < 4; j++)
                    mma16816h(acc[i][j], ah[i], bh[j][0], bh[j][1]);
        }
    };

    load_stage(0);
    store_stage(0);
    __syncthreads();

    for (int c = 0; c < G1_NC; c++) {
        if (c + 1 < G1_NC) load_stage((c + 1) * G1_KC);
        compute(c & 1);
        if (c + 1 < G1_NC) store_stage((c + 1) & 1);
        __syncthreads();
    }

    #pragma unroll
    for (int i = 0; i < 4; i++) {
        int r0 = row0 + wm * 64 + i * 16 + (lane >> 2);
        #pragma unroll
        for (int j = 0; j < 4; j++) {
            int cidx = col0 + wn * 32 + j * 8 + (lane & 3) * 2;
            if (r0 < NN)
                *reinterpret_cast<__half2*>(g_XW0h + (size_t)r0 * HD + cidx) =
                    __floats2half2_rn(acc[i][j][0], acc[i][j][1]);
            if (r0 + 8 < NN)
                *reinterpret_cast<__half2*>(g_XW0h + (size_t)(r0 + 8) * HD + cidx) =
                    __floats2half2_rn(acc[i][j][2], acc[i][j][3]);
        }
    }
}

// ---------------- SpMM1: H1 = relu(A @ XW0h) -> fp32, warp per row ----------------
__device__ __forceinline__ void fmah8(float* acc, float v, const uint4& q) {
    const __half2* h = reinterpret_cast<const __half2*>(&q);
    #pragma unroll
    for (int t = 0; t < 4; t++) {
        float2 f = __half22float2(h[t]);
        acc[2 * t]     = fmaf(v, f.x, acc[2 * t]);
        acc[2 * t + 1] = fmaf(v, f.y, acc[2 * t + 1]);
    }
}

__global__ void __launch_bounds__(256) spmm1_relu_kernel() {
    int w    = (blockIdx.x * blockDim.x + threadIdx.x) >> 5;
    int lane = threadIdx.x & 31;
    if (w >= NN) return;

    int s = g_rowptr[w], e = g_rowptr[w + 1];
    const uint4* Yh = reinterpret_cast<const uint4*>(g_XW0h);

    float acc[8];
    #pragma unroll
    for (int t = 0; t < 8; t++) acc[t] = 0.f;

    int i = s;
    for (; i + 8 <= e; i += 8) {
        int2 ed[8];
        uint4 q[8];
        #pragma unroll
        for (int u = 0; u < 8; u++) ed[u] = g_cedge[i + u];
        #pragma unroll
        for (int u = 0; u < 8; u++) q[u] = Yh[(size_t)ed[u].x * 32 + lane];
        #pragma unroll
        for (int u = 0; u < 8; u++) fmah8(acc, __int_as_float(ed[u].y), q[u]);
    }
    for (; i + 4 <= e; i += 4) {
        int2 e0 = g_cedge[i],     e1 = g_cedge[i + 1];
        int2 e2 = g_cedge[i + 2], e3 = g_cedge[i + 3];
        uint4 q0 = Yh[(size_t)e0.x * 32 + lane];
        uint4 q1 = Yh[(size_t)e1.x * 32 + lane];
        uint4 q2 = Yh[(size_t)e2.x * 32 + lane];
        uint4 q3 = Yh[(size_t)e3.x * 32 + lane];
        fmah8(acc, __int_as_float(e0.y), q0);
        fmah8(acc, __int_as_float(e1.y), q1);
        fmah8(acc, __int_as_float(e2.y), q2);
        fmah8(acc, __int_as_float(e3.y), q3);
    }
    for (; i < e; i++) {
        int2 ed = g_cedge[i];
        uint4 q = Yh[(size_t)ed.x * 32 + lane];
        fmah8(acc, __int_as_float(ed.y), q);
    }

    float* dst = g_H1 + (size_t)w * HD + lane * 8;
    *reinterpret_cast<float4*>(dst) =
        make_float4(fmaxf(acc[0], 0.f), fmaxf(acc[1], 0.f),
                    fmaxf(acc[2], 0.f), fmaxf(acc[3], 0.f));
    *reinterpret_cast<float4*>(dst + 4) =
        make_float4(fmaxf(acc[4], 0.f), fmaxf(acc[5], 0.f),
                    fmaxf(acc[6], 0.f), fmaxf(acc[7], 0.f));
}

// ---------------- GEMM2 via mma.sync split-bf16 (3 products): fp32 in/out ---------
#define G2_KC   32
#define G2_NC   (HD / G2_KC)          // 8
#define G2_STR  40
#define G2_AH   0
#define G2_AL   10240
#define G2_BH   20480
#define G2_BL   25600
#define G2_BUF  30720
#define G2_SMEM (2 * G2_BUF)

__global__ void __launch_bounds__(256) gemm2_mma_kernel() {
    extern __shared__ __align__(16) char smem[];
    uint32_t sb = smem_u32(smem);

    int tid  = threadIdx.x;
    int lane = tid & 31;
    int wid  = tid >> 5;
    int wm   = wid >> 1;
    int wn   = wid & 1;
    int row0 = blockIdx.x * 128;

    int ar8   = tid >> 3;
    int ac8   = (tid & 7) * 4;
    int b_row = tid >> 2;
    int b_kc  = (tid & 3) * 8;

    float4 aS[4];
    uint4  bhS, blS;

    uint32_t a_ld_off = (uint32_t)((wm * 32 + (lane & 15)) * G2_STR + ((lane >> 4) << 3)) * 2;
    uint32_t b_ld_off = (uint32_t)((wn * 32 + (lane & 7) + ((lane >> 4) << 3)) * G2_STR
                                   + (((lane >> 3) & 1) << 3)) * 2;

    float acc[2][4][4];
    #pragma unroll
    for (int i = 0; i < 2; i++)
        #pragma unroll
        for (int j = 0; j < 4; j++)
            #pragma unroll
            for (int t = 0; t < 4; t++) acc[i][j][t] = 0.f;

    auto load_stage = [&](int kt) {
        #pragma unroll
        for (int p = 0; p < 4; p++) {
            int r = row0 + ar8 + p * 32;
            aS[p] = (r < NN)
                ? *reinterpret_cast<const float4*>(g_H1 + (size_t)r * HD + kt + ac8)
                : make_float4(0.f, 0.f, 0.f, 0.f);
        }
        bhS = *reinterpret_cast<const uint4*>(g_W1t_hi + (size_t)b_row * HD + kt + b_kc);
        blS = *reinterpret_cast<const uint4*>(g_W1t_lo + (size_t)b_row * HD + kt + b_kc);
    };

    auto store_stage = [&](int buf) {
        char* base = smem + buf * G2_BUF;
        #pragma unroll
        for (int p = 0; p < 4; p++) {
            float4 v = aS[p];
            __nv_bfloat162 h01 = __floats2bfloat162_rn(v.x, v.y);
            __nv_bfloat162 h23 = __floats2bfloat162_rn(v.z, v.w);
            float2 f01 = __bfloat1622float2(h01);
            float2 f23 = __bfloat1622float2(h23);
            __nv_bfloat162 l01 = __floats2bfloat162_rn(v.x - f01.x, v.y - f01.y);
            __nv_bfloat162 l23 = __floats2bfloat162_rn(v.z - f23.x, v.w - f23.y);
            uint32_t off = (uint32_t)((ar8 + p * 32) * G2_STR + ac8) * 2;
            *reinterpret_cast<uint2*>(base + G2_AH + off) =
                make_uint2(*(uint32_t*)&h01, *(uint32_t*)&h23);
            *reinterpret_cast<uint2*>(base + G2_AL + off) =
                make_uint2(*(uint32_t*)&l01, *(uint32_t*)&l23);
        }
        uint32_t boff = (uint32_t)(b_row * G2_STR + b_kc) * 2;
        *reinterpret_cast<uint4*>(base + G2_BH + boff) = bhS;
        *reinterpret_cast<uint4*>(base + G2_BL + boff) = blS;
    };

    auto compute = [&](int buf) {
        uint32_t ab = sb + buf * G2_BUF;
        #pragma unroll
        for (int ks = 0; ks < 2; ks++) {
            uint32_t kso = (uint32_t)(ks * 16) * 2;
            uint32_t ah[2][4], al[2][4], bh[4][2], bl[4][2];
            #pragma unroll
            for (int i = 0; i < 2; i++) {
                uint32_t ao = ab + a_ld_off + kso + (uint32_t)(i * 16 * G2_STR) * 2;
                ldmx4(ah[i], ao + G2_AH);
                ldmx4(al[i], ao + G2_AL);
            }
            #pragma unroll
            for (int j2 = 0; j2 < 2; j2++) {
                uint32_t bo = ab + b_ld_off + kso + (uint32_t)(j2 * 16 * G2_STR) * 2;
                uint32_t t[4];
                ldmx4(t, bo + G2_BH);
                bh[j2 * 2][0] = t[0]; bh[j2 * 2][1] = t[1];
                bh[j2 * 2 + 1][0] = t[2]; bh[j2 * 2 + 1][1] = t[3];
                ldmx4(t, bo + G2_BL);
                bl[j2 * 2][0] = t[0]; bl[j2 * 2][1] = t[1];
                bl[j2 * 2 + 1][0] = t[2]; bl[j2 * 2 + 1][1] = t[3];
            }
            #pragma unroll
            for (int i = 0; i < 2; i++)
                #pragma unroll
                for (int j = 0; j < 4; j++) {
                    mma16816b(acc[i][j], ah[i], bh[j][0], bh[j][1]);
                    mma16816b(acc[i][j], ah[i], bl[j][0], bl[j][1]);
                    mma16816b(acc[i][j], al[i], bh[j][0], bh[j][1]);
                }
        }
    };

    load_stage(0);
    store_stage(0);
    __syncthreads();

    for (int c = 0; c < G2_NC; c++) {
        if (c + 1 < G2_NC) load_stage((c + 1) * G2_KC);
        compute(c & 1);
        if (c + 1 < G2_NC) store_stage((c + 1) & 1);
        __syncthreads();
    }

    #pragma unroll
    for (int i = 0; i < 2; i++) {
        int r0 = row0 + wm * 32 + i * 16 + (lane >> 2);
        #pragma unroll
        for (int j = 0; j < 4; j++) {
            int cidx = wn * 32 + j * 8 + (lane & 3) * 2;
            if (r0 < NN)
                *reinterpret_cast<float2*>(g_H1W1 + (size_t)r0 * FD + cidx) =
                    make_float2(acc[i][j][0], acc[i][j][1]);
            if (r0 + 8 < NN)
                *reinterpret_cast<float2*>(g_H1W1 + (size_t)(r0 + 8) * FD + cidx) =
                    make_float2(acc[i][j][2], acc[i][j][3]);
        }
    }
}

// ---------------- SpMM2 + softmax (fp32 gather) -----------------------------------
__global__ void __launch_bounds__(256) spmm2_softmax_kernel(float* __restrict__ out) {
    int w    = (blockIdx.x * blockDim.x + threadIdx.x) >> 5;
    int lane = threadIdx.x & 31;
    if (w >= NN) return;

    int s = g_rowptr[w], e = g_rowptr[w + 1];
    const float2* Y2 = reinterpret_cast<const float2*>(g_H1W1);

    float ax = 0.f, ay = 0.f;
    int i = s;
    for (; i + 4 <= e; i += 4) {
        int2 e0 = g_cedge[i],     e1 = g_cedge[i + 1];
        int2 e2 = g_cedge[i + 2], e3 = g_cedge[i + 3];
        float2 y0 = Y2[(size_t)e0.x * 32 + lane];
        float2 y1 = Y2[(size_t)e1.x * 32 + lane];
        float2 y2 = Y2[(size_t)e2.x * 32 + lane];
        float2 y3 = Y2[(size_t)e3.x * 32 + lane];
        float v0 = __int_as_float(e0.y), v1 = __int_as_float(e1.y);
        float v2 = __int_as_float(e2.y), v3 = __int_as_float(e3.y);
        ax = fmaf(v0, y0.x, ax); ay = fmaf(v0, y0.y, ay);
        ax = fmaf(v1, y1.x, ax); ay = fmaf(v1, y1.y, ay);
        ax = fmaf(v2, y2.x, ax); ay = fmaf(v2, y2.y, ay);
        ax = fmaf(v3, y3.x, ax); ay = fmaf(v3, y3.y, ay);
    }
    for (; i < e; i++) {
        int2 ed = g_cedge[i];
        float v = __int_as_float(ed.y);
        float2 y = Y2[(size_t)ed.x * 32 + lane];
        ax = fmaf(v, y.x, ax); ay = fmaf(v, y.y, ay);
    }

    float m = fmaxf(ax, ay);
    #pragma unroll
    for (int o = 16; o; o >>= 1) m = fmaxf(m, __shfl_xor_sync(0xffffffffu, m, o));
    float e0 = expf(ax - m), e1 = expf(ay - m);
    float sum = e0 + e1;
    #pragma unroll
    for (int o = 16; o; o >>= 1) sum += __shfl_xor_sync(0xffffffffu, sum, o);
    float inv = 1.f / sum;

    reinterpret_cast<float2*>(out)[(size_t)w * 32 + lane] = make_float2(e0 * inv, e1 * inv);
}

// ---------------- launcher ----------------------------------------------------------
extern "C" void kernel_launch(void* const* d_in, const int* in_sizes, int n_in,
                              void* d_out, int out_size) {
    const float* X  = (const float*)d_in[0];
    const int*   er = (const int*)d_in[1];
    const int*   ec = (const int*)d_in[2];
    const float* ev = (const float*)d_in[3];
    const float* W0 = (const float*)d_in[4];
    const float* W1 = (const float*)d_in[5];
    float* out = (float*)d_out;

    static cudaStream_t sB = nullptr;
    static cudaEvent_t evFork = nullptr, evJoin = nullptr;
    static bool init_done = false;
    if (!init_done) {
        cudaFuncSetAttribute(gemm1_mma_kernel,
                             cudaFuncAttributeMaxDynamicSharedMemorySize, G1_SMEM);
        cudaFuncSetAttribute(gemm2_mma_kernel,
                             cudaFuncAttributeMaxDynamicSharedMemorySize, G2_SMEM);
        cudaStreamCreateWithFlags(&sB, cudaStreamNonBlocking);
        cudaEventCreateWithFlags(&evFork, cudaEventDisableTiming);
        cudaEventCreateWithFlags(&evJoin, cudaEventDisableTiming);
        init_done = true;
    }

    // Fork: CSR build on side stream sB, concurrent with weight prep + GEMM1.
    cudaEventRecord(evFork, 0);
    cudaStreamWaitEvent(sB, evFork, 0);

    // --- branch B: CSR build (depends only on edges) ---
    zero_cnt_kernel<<<(NN + 255) / 256, 256, 0, sB>>>();
    hist_kernel<<<(EE / 4 + 255) / 256, 256, 0, sB>>>((const int4*)er);
    scan_kernel<<<1, 1024, 0, sB>>>();
    scatter_kernel<<<(EE + 255) / 256, 256, 0, sB>>>(er, ec, ev);
    cudaEventRecord(evJoin, sB);

    // --- branch A (main stream): weight prep + GEMM1 (depends only on X, W0, W1) ---
    w0_half_kernel<<<(K1 * HD + 255) / 256, 256>>>(W0);
    w1_split_kernel<<<(HD * FD + 255) / 256, 256>>>(W1);
    {
        dim3 grid((NN + 127) / 128, HD / 128);
        gemm1_mma_kernel<<<grid, 256, G1_SMEM>>>(X);
    }

    // Join: SpMM1 needs CSR + XW0h.
    cudaStreamWaitEvent(0, evJoin, 0);
    spmm1_relu_kernel<<<(NN * 32 + 255) / 256, 256>>>();

    // Layer 2
    gemm2_mma_kernel<<<(NN + 127) / 128, 256, G2_SMEM>>>();
    spmm2_softmax_kernel<<<(NN * 32 + 255) / 256, 256>>>(out);
}